// round 11
// baseline (speedup 1.0000x reference)
#include <cuda_runtime.h>
#include <cuda_fp16.h>

#define NN 50000
#define EE 800000
#define ET (EE + NN)   // edges + self loops
#define FULLM 0xffffffffu

__host__ __device__ constexpr int CDIV(int a, int b) { return (a + b - 1) / b; }

// ---------------- scratch (static __device__ globals; no allocs) -------------
__device__ __align__(16) int g_rowptr[NN + 4];
__device__ __align__(16) int g_cursor[NN];       // zero at call start (invariant)
__device__ int    g_csr[ET];
__device__ float4 g_hin4[NN * 8];        // node features [n][din] fp32, din<=32
__device__ __align__(128) __half g_hh[NN * 192];  // transformed features, fp16
__device__ float4 g_ae4[NN * 4];         // [n][16]: 0..5 src logits, 8..13 dst logits
__device__ float  g_wa[4 * 384];         // folded attention mats: [l][d*12+hh]

__device__ __forceinline__ float selu_f(float x) {
    const float sc = 1.0507009873554805f;
    const float al = 1.6732632423543772f;
    return x > 0.f ? sc * x : sc * al * (__expf(x) - 1.f);
}
__device__ __forceinline__ float lrelu(float x) { return x > 0.f ? x : 0.2f * x; }
__device__ __forceinline__ float f4c(const float4& v, int j) {
    return j == 0 ? v.x : j == 1 ? v.y : j == 2 ? v.z : v.w;
}
__device__ __forceinline__ void fma4(float4& a, const float4& v, float s) {
    a.x += v.x * s; a.y += v.y * s; a.z += v.z * s; a.w += v.w * s;
}
__device__ __forceinline__ uint2 f4_to_h4(float4 a) {
    __half2 lo = __floats2half2_rn(a.x, a.y);
    __half2 hi = __floats2half2_rn(a.z, a.w);
    uint2 r;
    r.x = *reinterpret_cast<unsigned*>(&lo);
    r.y = *reinterpret_cast<unsigned*>(&hi);
    return r;
}
__device__ __forceinline__ __half2 u2h(unsigned u) {
    return *reinterpret_cast<__half2*>(&u);
}

// ---------------- launch 0: count + lin0 + wa precompute --------------------
#define CNT_BLOCKS  CDIV(EE, 256)
#define LIN0_BLOCKS CDIV(NN * 16, 256)
__global__ __launch_bounds__(256) void k_count_lin0(
    const int* __restrict__ ei, const float* __restrict__ x,
    const float* __restrict__ lw, const float* __restrict__ lb,
    const float* __restrict__ W1, const float* __restrict__ AS1, const float* __restrict__ AD1,
    const float* __restrict__ W2, const float* __restrict__ AS2, const float* __restrict__ AD2,
    const float* __restrict__ W3, const float* __restrict__ AS3, const float* __restrict__ AD3,
    const float* __restrict__ W4, const float* __restrict__ AS4, const float* __restrict__ AD4) {
    if (blockIdx.x < CNT_BLOCKS) {
        int i = blockIdx.x * 256 + threadIdx.x;
        if (i < EE) atomicAdd(&g_cursor[ei[EE + i]], 1);
    } else if (blockIdx.x < CNT_BLOCKS + LIN0_BLOCKS) {
        int i = (blockIdx.x - CNT_BLOCKS) * 256 + threadIdx.x;
        if (i >= NN * 16) return;
        int n = i >> 4, c = i & 15;
        const float* xr = x + n * 10;
        const float* wr = lw + c * 10;
        float acc = lb[c];
        #pragma unroll
        for (int d = 0; d < 10; d++) acc += xr[d] * wr[d];
        reinterpret_cast<float*>(g_hin4)[i] = selu_f(acc);
    } else {
        const float* Ws[4]  = {W1, W2, W3, W4};
        const float* ASs[4] = {AS1, AS2, AS3, AS4};
        const float* ADs[4] = {AD1, AD2, AD3, AD4};
        const int din[4]  = {16, 32, 32, 16};
        const int dout[4] = {32, 32, 16, 2};
        for (int e = threadIdx.x; e < 4 * 384; e += 256) {
            int l = e / 384, r = e - l * 384, d = r / 12, hh = r - d * 12;
            if (d >= din[l]) continue;
            int head = hh % 6;
            int DO = dout[l], DI = din[l];
            const float* av = (hh < 6 ? ASs[l] : ADs[l]) + head * DO;
            const float* Wl = Ws[l];
            float s = 0.f;
            for (int o = 0; o < DO; o++) s += av[o] * Wl[(head * DO + o) * DI + d];
            g_wa[e] = s;
        }
    }
}

// ---------------- launch 1: scan, 4 elems/thread (adds self-loop +1) --------
__global__ void k_scan() {
    __shared__ int s_wtot[33];
    __shared__ int s_carry;
    int tid = threadIdx.x, lane = tid & 31, wid = tid >> 5;
    if (tid == 0) s_carry = 0;
    __syncthreads();
    const int4* cur4 = reinterpret_cast<const int4*>(g_cursor);
    int4* cw4 = reinterpret_cast<int4*>(g_cursor);
    int4* rp4 = reinterpret_cast<int4*>(g_rowptr);
    constexpr int N4 = NN / 4;       // 12500
    for (int base = 0; base < N4; base += 1024) {
        int i4 = base + tid;
        int4 v = {0, 0, 0, 0};
        if (i4 < N4) {
            v = cur4[i4];
            v.x++; v.y++; v.z++; v.w++;   // self loops
        }
        int t0 = v.x, t1 = t0 + v.y, t2 = t1 + v.z, t3 = t2 + v.w;
        int x = t3;
        #pragma unroll
        for (int o = 1; o < 32; o <<= 1) {
            int t = __shfl_up_sync(FULLM, x, o);
            if (lane >= o) x += t;
        }
        if (lane == 31) s_wtot[wid] = x;
        __syncthreads();
        if (wid == 0) {
            int w = s_wtot[lane];
            int y = w;
            #pragma unroll
            for (int o = 1; o < 32; o <<= 1) {
                int t = __shfl_up_sync(FULLM, y, o);
                if (lane >= o) y += t;
            }
            s_wtot[lane] = y - w;
            if (lane == 31) s_wtot[32] = y;
        }
        __syncthreads();
        int excl = s_carry + s_wtot[wid] + (x - t3);
        if (i4 < N4) {
            int4 r;
            r.x = excl; r.y = excl + t0; r.z = excl + t1; r.w = excl + t2;
            rp4[i4] = r;
            cw4[i4] = r;
        }
        int btot = s_wtot[32];
        __syncthreads();
        if (tid == 0) s_carry += btot;
        __syncthreads();
    }
    if (tid == 0) g_rowptr[NN] = s_carry;
}

// ---------------- transform / alpha device functions ------------------------
#define TILES 8
template <int DIN, int DOUT, int STRIDE>
__device__ __forceinline__ void dev_transform(float* s_buf, int blk,
                                              const float* __restrict__ W) {
    constexpr int HD = 6 * DOUT;
    constexpr int C4 = HD / 4;
    constexpr int C4S = STRIDE / 4;
    constexpr int TOT = (NN / 4) * C4S;
    for (int i = threadIdx.x; i < DIN * HD; i += 256) {
        int k = i / DIN, d = i - k * DIN;
        s_buf[d * HD + k] = W[i];
    }
    __syncthreads();
    #pragma unroll
    for (int rep = 0; rep < TILES; rep++) {
        int t = (blk * TILES + rep) * 256 + threadIdx.x;
        if (t >= TOT) return;
        int c4 = t % C4S, nb = t / C4S;
        int n0 = nb * 4;
        float4 acc0 = {0,0,0,0}, acc1 = {0,0,0,0}, acc2 = {0,0,0,0}, acc3 = {0,0,0,0};
        if (c4 < C4) {
            const float4* x4 = g_hin4;
            const float4* w4 = reinterpret_cast<const float4*>(s_buf);
            #pragma unroll
            for (int dc = 0; dc < DIN / 4; dc++) {
                float4 xv0 = x4[(n0 + 0) * (DIN / 4) + dc];
                float4 xv1 = x4[(n0 + 1) * (DIN / 4) + dc];
                float4 xv2 = x4[(n0 + 2) * (DIN / 4) + dc];
                float4 xv3 = x4[(n0 + 3) * (DIN / 4) + dc];
                #pragma unroll
                for (int j = 0; j < 4; j++) {
                    float4 wv = w4[(dc * 4 + j) * C4 + c4];
                    fma4(acc0, wv, f4c(xv0, j));
                    fma4(acc1, wv, f4c(xv1, j));
                    fma4(acc2, wv, f4c(xv2, j));
                    fma4(acc3, wv, f4c(xv3, j));
                }
            }
        }
        __half* hb = g_hh;
        *reinterpret_cast<uint2*>(hb + (size_t)(n0 + 0) * STRIDE + c4 * 4) = f4_to_h4(acc0);
        *reinterpret_cast<uint2*>(hb + (size_t)(n0 + 1) * STRIDE + c4 * 4) = f4_to_h4(acc1);
        *reinterpret_cast<uint2*>(hb + (size_t)(n0 + 2) * STRIDE + c4 * 4) = f4_to_h4(acc2);
        *reinterpret_cast<uint2*>(hb + (size_t)(n0 + 3) * STRIDE + c4 * 4) = f4_to_h4(acc3);
    }
}

template <int DIN, int LAYER>
__device__ __forceinline__ void dev_alpha(float* s_buf, int blk) {
    for (int i = threadIdx.x; i < DIN * 12; i += 256)
        s_buf[i] = g_wa[LAYER * 384 + i];
    __syncthreads();
    #pragma unroll
    for (int rep = 0; rep < TILES; rep++) {
        int t2 = (blk * TILES + rep) * 256 + threadIdx.x;
        if (t2 >= NN * 12) return;
        int n = t2 / 12, hh = t2 - n * 12;
        const float4* xr4 = g_hin4 + (size_t)n * (DIN / 4);
        float acc = 0.f;
        #pragma unroll
        for (int d4 = 0; d4 < DIN / 4; d4++) {
            float4 xv = xr4[d4];
            acc += xv.x * s_buf[(d4 * 4 + 0) * 12 + hh]
                 + xv.y * s_buf[(d4 * 4 + 1) * 12 + hh]
                 + xv.z * s_buf[(d4 * 4 + 2) * 12 + hh]
                 + xv.w * s_buf[(d4 * 4 + 3) * 12 + hh];
        }
        reinterpret_cast<float*>(g_ae4)[n * 16 + (hh < 6 ? hh : hh + 2)] = acc;
    }
}

#define NBA2 CDIV(CDIV(NN * 12, 256), TILES)

// ---------------- launch 2: scatter + feat layer 1, fused -------------------
#define NBT1 CDIV(CDIV((NN / 4) * 48, 256), TILES)
#define SCAT_BLOCKS CDIV(ET, 256)
__global__ __launch_bounds__(256) void k_scatter_feat1(const int* __restrict__ ei,
                                                       const float* __restrict__ W) {
    __shared__ float s_buf[16 * 192];
    if (blockIdx.x < SCAT_BLOCKS) {
        int i = blockIdx.x * 256 + threadIdx.x;
        if (i >= ET) return;
        int s, d;
        if (i < EE) { s = ei[i]; d = ei[EE + i]; }
        else        { s = d = i - EE; }
        int pos = atomicAdd(&g_cursor[d], 1);
        g_csr[pos] = s;
    } else if (blockIdx.x < SCAT_BLOCKS + NBT1) {
        dev_transform<16, 32, 192>(s_buf, blockIdx.x - SCAT_BLOCKS, W);
    } else {
        dev_alpha<16, 0>(s_buf, blockIdx.x - SCAT_BLOCKS - NBT1);
    }
}

// ---------------- per-layer feat (layers 2-4) -------------------------------
template <int DIN, int DOUT, int STRIDE, int LAYER, bool ZERO_CURSOR>
__global__ __launch_bounds__(256) void k_feat(const float* __restrict__ W) {
    __shared__ float s_buf[DIN * 6 * DOUT];
    constexpr int NBT = CDIV(CDIV((NN / 4) * (STRIDE / 4), 256), TILES);
    if (blockIdx.x < NBT) {
        dev_transform<DIN, DOUT, STRIDE>(s_buf, blockIdx.x, W);
    } else if (blockIdx.x < NBT + NBA2) {
        dev_alpha<DIN, LAYER>(s_buf, blockIdx.x - NBT);
    } else if (ZERO_CURSOR) {
        int i = (blockIdx.x - NBT - NBA2) * 256 + threadIdx.x;
        if (i < NN) g_cursor[i] = 0;
    }
}

// ---------------- fused GAT -------------------------------------------------
// per-warp smem (DOUT>2): [0,216) alpha half2 table (head-major stride 36),
//                         [216,248) per-edge byte offsets (int)
template <int DOUT>
__global__ __launch_bounds__(256, 6) void k_gat(const float* __restrict__ bias,
                                                float* __restrict__ out) {
    __shared__ float s_red[(DOUT > 2) ? 8 * 256 : 8];
    int w = threadIdx.x >> 5, lane = threadIdx.x & 31;
    int n = blockIdx.x * 8 + w;           // grid = NN/8 exactly
    int start = g_rowptr[n], end = g_rowptr[n + 1];
    int deg = end - start;

    const float4* ae4 = g_ae4;
    const float*  aef = reinterpret_cast<const float*>(g_ae4);
    float4 d03 = ae4[n * 4 + 2];
    float4 d45 = ae4[n * 4 + 3];
    float adh[6] = {d03.x, d03.y, d03.z, d03.w, d45.x, d45.y};
    float* sw = s_red + ((DOUT > 2) ? w * 256 : 0);
    const uint4* gh = reinterpret_cast<const uint4*>(g_hh);

    // ================= DOUT == 2 (HD=12, stride 16 halves) =================
    if constexpr (DOUT == 2) {
        float acc[12];
        #pragma unroll
        for (int k = 0; k < 12; k++) acc[k] = 0.f;
        if (deg <= 32) {
            int s = 0; bool act = lane < deg;
            if (act) s = g_csr[start + lane];
            float p[6], S[6];
            if (act) {
                float4 a03 = ae4[s * 4 + 0], a45 = ae4[s * 4 + 1];
                p[0] = __expf(lrelu(a03.x + adh[0]));
                p[1] = __expf(lrelu(a03.y + adh[1]));
                p[2] = __expf(lrelu(a03.z + adh[2]));
                p[3] = __expf(lrelu(a03.w + adh[3]));
                p[4] = __expf(lrelu(a45.x + adh[4]));
                p[5] = __expf(lrelu(a45.y + adh[5]));
            } else {
                #pragma unroll
                for (int h = 0; h < 6; h++) p[h] = 0.f;
            }
            #pragma unroll
            for (int h = 0; h < 6; h++) S[h] = p[h];
            #pragma unroll
            for (int h = 0; h < 6; h++)
                #pragma unroll
                for (int o = 16; o > 0; o >>= 1)
                    S[h] += __shfl_xor_sync(FULLM, S[h], o);
            float al[6];
            #pragma unroll
            for (int h = 0; h < 6; h++) al[h] = p[h] * (1.f / S[h]);
            if (act) {
                const uint4* hp = gh + s * 2;
                uint4 u0 = hp[0], u1 = hp[1];
                float2 f;
                f = __half22float2(u2h(u0.x)); acc[0] = f.x * al[0]; acc[1] = f.y * al[0];
                f = __half22float2(u2h(u0.y)); acc[2] = f.x * al[1]; acc[3] = f.y * al[1];
                f = __half22float2(u2h(u0.z)); acc[4] = f.x * al[2]; acc[5] = f.y * al[2];
                f = __half22float2(u2h(u0.w)); acc[6] = f.x * al[3]; acc[7] = f.y * al[3];
                f = __half22float2(u2h(u1.x)); acc[8] = f.x * al[4]; acc[9] = f.y * al[4];
                f = __half22float2(u2h(u1.y)); acc[10] = f.x * al[5]; acc[11] = f.y * al[5];
            }
        } else {
            float S[6];
            #pragma unroll
            for (int h = 0; h < 6; h++) S[h] = 0.f;
            for (int j = start + lane; j < end; j += 32) {
                int s = g_csr[j];
                float4 a03 = ae4[s * 4 + 0], a45 = ae4[s * 4 + 1];
                S[0] += __expf(lrelu(a03.x + adh[0]));
                S[1] += __expf(lrelu(a03.y + adh[1]));
                S[2] += __expf(lrelu(a03.z + adh[2]));
                S[3] += __expf(lrelu(a03.w + adh[3]));
                S[4] += __expf(lrelu(a45.x + adh[4]));
                S[5] += __expf(lrelu(a45.y + adh[5]));
            }
            #pragma unroll
            for (int h = 0; h < 6; h++)
                #pragma unroll
                for (int o = 16; o > 0; o >>= 1)
                    S[h] += __shfl_xor_sync(FULLM, S[h], o);
            float inv[6];
            #pragma unroll
            for (int h = 0; h < 6; h++) inv[h] = 1.f / S[h];
            for (int j = start + lane; j < end; j += 32) {
                int s = g_csr[j];
                float4 a03 = ae4[s * 4 + 0], a45 = ae4[s * 4 + 1];
                float al[6];
                al[0] = __expf(lrelu(a03.x + adh[0])) * inv[0];
                al[1] = __expf(lrelu(a03.y + adh[1])) * inv[1];
                al[2] = __expf(lrelu(a03.z + adh[2])) * inv[2];
                al[3] = __expf(lrelu(a03.w + adh[3])) * inv[3];
                al[4] = __expf(lrelu(a45.x + adh[4])) * inv[4];
                al[5] = __expf(lrelu(a45.y + adh[5])) * inv[5];
                const uint4* hp = gh + s * 2;
                uint4 u0 = hp[0], u1 = hp[1];
                float2 f;
                f = __half22float2(u2h(u0.x)); acc[0] += f.x * al[0]; acc[1] += f.y * al[0];
                f = __half22float2(u2h(u0.y)); acc[2] += f.x * al[1]; acc[3] += f.y * al[1];
                f = __half22float2(u2h(u0.z)); acc[4] += f.x * al[2]; acc[5] += f.y * al[2];
                f = __half22float2(u2h(u0.w)); acc[6] += f.x * al[3]; acc[7] += f.y * al[3];
                f = __half22float2(u2h(u1.x)); acc[8] += f.x * al[4]; acc[9] += f.y * al[4];
                f = __half22float2(u2h(u1.y)); acc[10] += f.x * al[5]; acc[11] += f.y * al[5];
            }
        }
        float q0 = acc[0] + acc[2] + acc[4] + acc[6] + acc[8] + acc[10];
        float q1 = acc[1] + acc[3] + acc[5] + acc[7] + acc[9] + acc[11];
        #pragma unroll
        for (int o = 16; o > 0; o >>= 1) {
            q0 += __shfl_xor_sync(FULLM, q0, o);
            q1 += __shfl_xor_sync(FULLM, q1, o);
        }
        if (lane < 2) {
            float v = lane ? q1 : q0;
            out[n * 2 + lane] = selu_f(v * (1.f / 6.f) + bias[lane]);
        }
        return;
    }

    // ================= DOUT == 32 / 16 =================
    bool actl = lane < 24;
    int hidx, ll = 0, eo = 0;
    if constexpr (DOUT == 32) {
        hidx = actl ? (lane >> 2) : 0;
    } else {
        ll = actl ? (lane % 12) : 0;
        eo = actl ? (lane / 12) : 0;
        hidx = ll >> 1;
    }
    constexpr int NU4 = (DOUT == 32) ? 24 : 12;   // uint4 per node row
    constexpr int ROWB = NU4 * 16;                // row bytes
    float f[8];
    #pragma unroll
    for (int k = 0; k < 8; k++) f[k] = 0.f;
    unsigned* swu = reinterpret_cast<unsigned*>(sw);
    int* soffu = reinterpret_cast<int*>(sw + 216);

    if (deg <= 32) {
        // ---- fast path: lane-per-edge softmax (no max shift) ----
        int s = 0; bool act = lane < deg;
        if (act) s = g_csr[start + lane];
        float p[6], S[6];
        if (act) {
            float4 a03 = ae4[s * 4 + 0], a45 = ae4[s * 4 + 1];
            p[0] = __expf(lrelu(a03.x + adh[0]));
            p[1] = __expf(lrelu(a03.y + adh[1]));
            p[2] = __expf(lrelu(a03.z + adh[2]));
            p[3] = __expf(lrelu(a03.w + adh[3]));
            p[4] = __expf(lrelu(a45.x + adh[4]));
            p[5] = __expf(lrelu(a45.y + adh[5]));
        } else {
            #pragma unroll
            for (int h = 0; h < 6; h++) p[h] = 0.f;
        }
        #pragma unroll
        for (int h = 0; h < 6; h++) S[h] = p[h];
        #pragma unroll
        for (int h = 0; h < 6; h++)
            #pragma unroll
            for (int o = 16; o > 0; o >>= 1)
                S[h] += __shfl_xor_sync(FULLM, S[h], o);
        // stage normalized alphas (broadcast half2) + byte offsets
        #pragma unroll
        for (int h = 0; h < 6; h++) {
            __half2 ah = __float2half2_rn(p[h] * (1.f / S[h]));
            swu[h * 36 + lane] = *reinterpret_cast<unsigned*>(&ah);
        }
        soffu[lane] = s * ROWB;          // padded lanes: s=0, alpha=0
        __syncwarp();

        int degR = (deg + 7) & ~7;       // padded edges have alpha=0

        if constexpr (DOUT == 32) {
            const char* baseb = reinterpret_cast<const char*>(gh) + lane * 16;
            for (int j = 0; j < degR; j += 8) {
                uint4 offa = *reinterpret_cast<const uint4*>(&soffu[j]);
                uint4 offb = *reinterpret_cast<const uint4*>(&soffu[j + 4]);
                uint4 aua = *reinterpret_cast<const uint4*>(&swu[hidx * 36 + j]);
                uint4 aub = *reinterpret_cast<const uint4*>(&swu[hidx * 36 + j + 4]);
                uint4 v0 = {0,0,0,0}, v1 = {0,0,0,0}, v2 = {0,0,0,0}, v3 = {0,0,0,0};
                if (actl) {
                    v0 = *reinterpret_cast<const uint4*>(baseb + offa.x);
                    v1 = *reinterpret_cast<const uint4*>(baseb + offa.y);
                    v2 = *reinterpret_cast<const uint4*>(baseb + offa.z);
                    v3 = *reinterpret_cast<const uint4*>(baseb + offa.w);
                }
                __half2 a0 = u2h(aua.x), a1 = u2h(aua.y), a2 = u2h(aua.z), a3 = u2h(aua.w);
                __half2 g0 = __hmul2(u2h(v0.x), a0);
                __half2 g1 = __hmul2(u2h(v0.y), a0);
                __half2 g2 = __hmul2(u2h(v0.z), a0);
                __half2 g3 = __hmul2(u2h(v0.w), a0);
                g0 = __hfma2(u2h(v1.x), a1, g0);
                g1 = __hfma2(u2h(v1.y), a1, g1);
                g2 = __hfma2(u2h(v1.z), a1, g2);
                g3 = __hfma2(u2h(v1.w), a1, g3);
                g0 = __hfma2(u2h(v2.x), a2, g0);
                g1 = __hfma2(u2h(v2.y), a2, g1);
                g2 = __hfma2(u2h(v2.z), a2, g2);
                g3 = __hfma2(u2h(v2.w), a2, g3);
                g0 = __hfma2(u2h(v3.x), a3, g0);
                g1 = __hfma2(u2h(v3.y), a3, g1);
                g2 = __hfma2(u2h(v3.z), a3, g2);
                g3 = __hfma2(u2h(v3.w), a3, g3);
                uint4 w0 = {0,0,0,0}, w1 = {0,0,0,0}, w2 = {0,0,0,0}, w3 = {0,0,0,0};
                if (actl) {
                    w0 = *reinterpret_cast<const uint4*>(baseb + offb.x);
                    w1 = *reinterpret_cast<const uint4*>(baseb + offb.y);
                    w2 = *reinterpret_cast<const uint4*>(baseb + offb.z);
                    w3 = *reinterpret_cast<const uint4*>(baseb + offb.w);
                }
                __half2 b0 = u2h(aub.x), b1 = u2h(aub.y), b2 = u2h(aub.z), b3 = u2h(aub.w);
                g0 = __hfma2(u2h(w0.x), b0, g0);
                g1 = __hfma2(u2h(w0.y), b0, g1);
                g2 = __hfma2(u2h(w0.z), b0, g2);
                g3 = __hfma2(u2h(w0.w), b0, g3);
                g0 = __hfma2(u2h(w1.x), b1, g0);
                g1 = __hfma2(u2h(w1.y), b1, g1);
                g2 = __hfma2(u2h(w1.z), b1, g2);
                g3 = __hfma2(u2h(w1.w), b1, g3);
                g0 = __hfma2(u2h(w2.x), b2, g0);
                g1 = __hfma2(u2h(w2.y), b2, g1);
                g2 = __hfma2(u2h(w2.z), b2, g2);
                g3 = __hfma2(u2h(w2.w), b2, g3);
                g0 = __hfma2(u2h(w3.x), b3, g0);
                g1 = __hfma2(u2h(w3.y), b3, g1);
                g2 = __hfma2(u2h(w3.z), b3, g2);
                g3 = __hfma2(u2h(w3.w), b3, g3);
                float2 t;
                t = __half22float2(g0); f[0] += t.x; f[1] += t.y;
                t = __half22float2(g1); f[2] += t.x; f[3] += t.y;
                t = __half22float2(g2); f[4] += t.x; f[5] += t.y;
                t = __half22float2(g3); f[6] += t.x; f[7] += t.y;
            }
        } else { // DOUT == 16: lanes split 2 edges x 12 dims, 8 edges per iter
            const char* baseb = reinterpret_cast<const char*>(gh) + ll * 16;
            for (int j = 0; j < degR; j += 8) {
                int o0 = soffu[j + eo],     o1 = soffu[j + 2 + eo];
                int o2 = soffu[j + 4 + eo], o3 = soffu[j + 6 + eo];
                __half2 a0 = u2h(actl ? swu[hidx * 36 + j + eo] : 0u);
                __half2 a1 = u2h(actl ? swu[hidx * 36 + j + 2 + eo] : 0u);
                __half2 a2 = u2h(actl ? swu[hidx * 36 + j + 4 + eo] : 0u);
                __half2 a3 = u2h(actl ? swu[hidx * 36 + j + 6 + eo] : 0u);
                uint4 v0 = {0,0,0,0}, v1 = {0,0,0,0}, v2 = {0,0,0,0}, v3 = {0,0,0,0};
                if (actl) {
                    v0 = *reinterpret_cast<const uint4*>(baseb + o0);
                    v1 = *reinterpret_cast<const uint4*>(baseb + o1);
                    v2 = *reinterpret_cast<const uint4*>(baseb + o2);
                    v3 = *reinterpret_cast<const uint4*>(baseb + o3);
                }
                __half2 g0 = __hmul2(u2h(v0.x), a0);
                __half2 g1 = __hmul2(u2h(v0.y), a0);
                __half2 g2 = __hmul2(u2h(v0.z), a0);
                __half2 g3 = __hmul2(u2h(v0.w), a0);
                g0 = __hfma2(u2h(v1.x), a1, g0);
                g1 = __hfma2(u2h(v1.y), a1, g1);
                g2 = __hfma2(u2h(v1.z), a1, g2);
                g3 = __hfma2(u2h(v1.w), a1, g3);
                g0 = __hfma2(u2h(v2.x), a2, g0);
                g1 = __hfma2(u2h(v2.y), a2, g1);
                g2 = __hfma2(u2h(v2.z), a2, g2);
                g3 = __hfma2(u2h(v2.w), a2, g3);
                g0 = __hfma2(u2h(v3.x), a3, g0);
                g1 = __hfma2(u2h(v3.y), a3, g1);
                g2 = __hfma2(u2h(v3.z), a3, g2);
                g3 = __hfma2(u2h(v3.w), a3, g3);
                float2 t;
                t = __half22float2(g0); f[0] += t.x; f[1] += t.y;
                t = __half22float2(g1); f[2] += t.x; f[3] += t.y;
                t = __half22float2(g2); f[4] += t.x; f[5] += t.y;
                t = __half22float2(g3); f[6] += t.x; f[7] += t.y;
            }
        }
    } else {
        // ---- slow path (deg > 32, rare): fp32 math ----
        float S[6];
        #pragma unroll
        for (int h = 0; h < 6; h++) S[h] = 0.f;
        for (int j = start + lane; j < end; j += 32) {
            int s = g_csr[j];
            float4 a03 = ae4[s * 4 + 0], a45 = ae4[s * 4 + 1];
            S[0] += __expf(lrelu(a03.x + adh[0]));
            S[1] += __expf(lrelu(a03.y + adh[1]));
            S[2] += __expf(lrelu(a03.z + adh[2]));
            S[3] += __expf(lrelu(a03.w + adh[3]));
            S[4] += __expf(lrelu(a45.x + adh[4]));
            S[5] += __expf(lrelu(a45.y + adh[5]));
        }
        #pragma unroll
        for (int h = 0; h < 6; h++)
            #pragma unroll
            for (int o = 16; o > 0; o >>= 1)
                S[h] += __shfl_xor_sync(FULLM, S[h], o);
        float inv_sel = 0.f, ad_sel = 0.f;
        #pragma unroll
        for (int h = 0; h < 6; h++)
            if (hidx == h) { inv_sel = 1.f / S[h]; ad_sel = adh[h]; }

        bool act_agg = (DOUT == 32) ? actl : (actl && eo == 0);
        int dlane = (DOUT == 32) ? lane : ll;
        for (int j = start; j < end; j++) {
            int s0 = g_csr[j];
            float a = 0.f;
            uint4 v = {0,0,0,0};
            if (act_agg) {
                float e = lrelu(aef[s0 * 16 + hidx] + ad_sel);
                a = __expf(e) * inv_sel;
                v = gh[(size_t)s0 * NU4 + dlane];
            }
            float2 t;
            t = __half22float2(u2h(v.x)); f[0] += t.x * a; f[1] += t.y * a;
            t = __half22float2(u2h(v.y)); f[2] += t.x * a; f[3] += t.y * a;
            t = __half22float2(u2h(v.z)); f[4] += t.x * a; f[5] += t.y * a;
            t = __half22float2(u2h(v.w)); f[6] += t.x * a; f[7] += t.y * a;
        }
    }

    // ---- common epilogue: smem transpose, head mean + bias + SELU ----
    __syncwarp();
    if constexpr (DOUT == 32) {
        if (actl) {
            int b = lane * 8;
            #pragma unroll
            for (int k = 0; k < 8; k++) sw[b + k] = f[k];
        }
        __syncwarp();
        float o0 = sw[lane] + sw[32 + lane] + sw[64 + lane] +
                   sw[96 + lane] + sw[128 + lane] + sw[160 + lane];
        out[n * 32 + lane] = selu_f(o0 * (1.f / 6.f) + bias[lane]);
    } else {
        if (actl) {
            int b = eo * 96 + ll * 8;
            #pragma unroll
            for (int k = 0; k < 8; k++) sw[b + k] = f[k];
        }
        __syncwarp();
        if (lane < 16) {
            float o0 = 0.f;
            #pragma unroll
            for (int h = 0; h < 6; h++)
                o0 += sw[h * 16 + lane] + sw[96 + h * 16 + lane];
            out[n * 16 + lane] = selu_f(o0 * (1.f / 6.f) + bias[lane]);
        }
    }
}

// ---------------- host launcher ---------------------------------------------
extern "C" void kernel_launch(void* const* d_in, const int* in_sizes, int n_in,
                              void* d_out, int out_size) {
    (void)in_sizes; (void)n_in; (void)out_size;
    const float* x     = (const float*)d_in[0];
    const int*   ei    = (const int*)d_in[1];
    const float* lin_w = (const float*)d_in[2];
    const float* lin_b = (const float*)d_in[3];
    const float* W[4]  = { (const float*)d_in[4],  (const float*)d_in[8],
                           (const float*)d_in[12], (const float*)d_in[16] };
    const float* AS[4] = { (const float*)d_in[5],  (const float*)d_in[9],
                           (const float*)d_in[13], (const float*)d_in[17] };
    const float* AD[4] = { (const float*)d_in[6],  (const float*)d_in[10],
                           (const float*)d_in[14], (const float*)d_in[18] };
    const float* B[4]  = { (const float*)d_in[7],  (const float*)d_in[11],
                           (const float*)d_in[15], (const float*)d_in[19] };
    float* out = (float*)d_out;

    float* g_hin_ptr = nullptr;
    cudaGetSymbolAddress((void**)&g_hin_ptr, g_hin4);

    const int gat_blocks = NN / 8;

    // 0: count + lin0 + wa
    k_count_lin0<<<CNT_BLOCKS + LIN0_BLOCKS + 1, 256>>>(
        ei, x, lin_w, lin_b,
        W[0], AS[0], AD[0], W[1], AS[1], AD[1],
        W[2], AS[2], AD[2], W[3], AS[3], AD[3]);
    // 1: scan
    k_scan<<<1, 1024>>>();
    // 2: scatter + feat layer 1 (fused, independent block ranges)
    k_scatter_feat1<<<SCAT_BLOCKS + NBT1 + NBA2, 256>>>(ei, W[0]);
    // 3: gat layer 1   <- ncu capture target
    k_gat<32><<<gat_blocks, 256>>>(B[0], g_hin_ptr);
    // 4-5: layer 2
    {
        constexpr int nbt = CDIV(CDIV((NN / 4) * 48, 256), TILES);
        k_feat<32, 32, 192, 1, false><<<nbt + NBA2, 256>>>(W[1]);
    }
    k_gat<32><<<gat_blocks, 256>>>(B[1], g_hin_ptr);
    // 6-7: layer 3
    {
        constexpr int nbt = CDIV(CDIV((NN / 4) * 24, 256), TILES);
        k_feat<32, 16, 96, 2, false><<<nbt + NBA2, 256>>>(W[2]);
    }
    k_gat<16><<<gat_blocks, 256>>>(B[2], g_hin_ptr);
    // 8-9: layer 4 (+cursor re-zero for next call)
    {
        constexpr int nbt = CDIV(CDIV((NN / 4) * 4, 256), TILES);
        k_feat<16, 2, 16, 3, true><<<nbt + NBA2 + CDIV(NN, 256), 256>>>(W[3]);
    }
    k_gat<2><<<gat_blocks, 256>>>(B[3], out);
}

// round 13
// speedup vs baseline: 1.0011x; 1.0011x over previous
#include <cuda_runtime.h>
#include <cuda_fp16.h>

#define NN 50000
#define EE 800000
#define ET (EE + NN)   // edges + self loops
#define FULLM 0xffffffffu

__host__ __device__ constexpr int CDIV(int a, int b) { return (a + b - 1) / b; }

// ---------------- scratch (static __device__ globals; no allocs) -------------
__device__ __align__(16) int g_rowptr[NN + 4];
__device__ __align__(16) int g_cursor[NN];       // zero at call start (invariant)
__device__ int    g_csr[ET];
__device__ float4 g_hin4[NN * 8];        // node features [n][din] fp32, din<=32
__device__ __align__(128) __half g_hh[NN * 192];  // transformed features, fp16
__device__ float4 g_ae4[NN * 4];         // [n][16]: 0..5 src logits, 8..13 dst logits
__device__ float  g_wa[4 * 384];         // folded attention mats: [l][d*12+hh]

__device__ __forceinline__ float selu_f(float x) {
    const float sc = 1.0507009873554805f;
    const float al = 1.6732632423543772f;
    return x > 0.f ? sc * x : sc * al * (__expf(x) - 1.f);
}
__device__ __forceinline__ float lrelu(float x) { return x > 0.f ? x : 0.2f * x; }
__device__ __forceinline__ float f4c(const float4& v, int j) {
    return j == 0 ? v.x : j == 1 ? v.y : j == 2 ? v.z : v.w;
}
__device__ __forceinline__ void fma4(float4& a, const float4& v, float s) {
    a.x += v.x * s; a.y += v.y * s; a.z += v.z * s; a.w += v.w * s;
}
__device__ __forceinline__ uint2 f4_to_h4(float4 a) {
    __half2 lo = __floats2half2_rn(a.x, a.y);
    __half2 hi = __floats2half2_rn(a.z, a.w);
    uint2 r;
    r.x = *reinterpret_cast<unsigned*>(&lo);
    r.y = *reinterpret_cast<unsigned*>(&hi);
    return r;
}
__device__ __forceinline__ __half2 u2h(unsigned u) {
    return *reinterpret_cast<__half2*>(&u);
}

// ---------------- launch 0: count + lin0 + wa precompute --------------------
#define CNT_BLOCKS  CDIV(EE, 256)
#define LIN0_BLOCKS CDIV(NN * 16, 256)
__global__ __launch_bounds__(256) void k_count_lin0(
    const int* __restrict__ ei, const float* __restrict__ x,
    const float* __restrict__ lw, const float* __restrict__ lb,
    const float* __restrict__ W1, const float* __restrict__ AS1, const float* __restrict__ AD1,
    const float* __restrict__ W2, const float* __restrict__ AS2, const float* __restrict__ AD2,
    const float* __restrict__ W3, const float* __restrict__ AS3, const float* __restrict__ AD3,
    const float* __restrict__ W4, const float* __restrict__ AS4, const float* __restrict__ AD4) {
    if (blockIdx.x < CNT_BLOCKS) {
        int i = blockIdx.x * 256 + threadIdx.x;
        if (i < EE) atomicAdd(&g_cursor[ei[EE + i]], 1);
    } else if (blockIdx.x < CNT_BLOCKS + LIN0_BLOCKS) {
        int i = (blockIdx.x - CNT_BLOCKS) * 256 + threadIdx.x;
        if (i >= NN * 16) return;
        int n = i >> 4, c = i & 15;
        const float* xr = x + n * 10;
        const float* wr = lw + c * 10;
        float acc = lb[c];
        #pragma unroll
        for (int d = 0; d < 10; d++) acc += xr[d] * wr[d];
        reinterpret_cast<float*>(g_hin4)[i] = selu_f(acc);
    } else {
        const float* Ws[4]  = {W1, W2, W3, W4};
        const float* ASs[4] = {AS1, AS2, AS3, AS4};
        const float* ADs[4] = {AD1, AD2, AD3, AD4};
        const int din[4]  = {16, 32, 32, 16};
        const int dout[4] = {32, 32, 16, 2};
        for (int e = threadIdx.x; e < 4 * 384; e += 256) {
            int l = e / 384, r = e - l * 384, d = r / 12, hh = r - d * 12;
            if (d >= din[l]) continue;
            int head = hh % 6;
            int DO = dout[l], DI = din[l];
            const float* av = (hh < 6 ? ASs[l] : ADs[l]) + head * DO;
            const float* Wl = Ws[l];
            float s = 0.f;
            for (int o = 0; o < DO; o++) s += av[o] * Wl[(head * DO + o) * DI + d];
            g_wa[e] = s;
        }
    }
}

// ---------------- launch 1: scan, 4 elems/thread (adds self-loop +1) --------
__global__ void k_scan() {
    __shared__ int s_wtot[33];
    __shared__ int s_carry;
    int tid = threadIdx.x, lane = tid & 31, wid = tid >> 5;
    if (tid == 0) s_carry = 0;
    __syncthreads();
    const int4* cur4 = reinterpret_cast<const int4*>(g_cursor);
    int4* cw4 = reinterpret_cast<int4*>(g_cursor);
    int4* rp4 = reinterpret_cast<int4*>(g_rowptr);
    constexpr int N4 = NN / 4;       // 12500
    for (int base = 0; base < N4; base += 1024) {
        int i4 = base + tid;
        int4 v = {0, 0, 0, 0};
        if (i4 < N4) {
            v = cur4[i4];
            v.x++; v.y++; v.z++; v.w++;   // self loops
        }
        int t0 = v.x, t1 = t0 + v.y, t2 = t1 + v.z, t3 = t2 + v.w;
        int x = t3;
        #pragma unroll
        for (int o = 1; o < 32; o <<= 1) {
            int t = __shfl_up_sync(FULLM, x, o);
            if (lane >= o) x += t;
        }
        if (lane == 31) s_wtot[wid] = x;
        __syncthreads();
        if (wid == 0) {
            int w = s_wtot[lane];
            int y = w;
            #pragma unroll
            for (int o = 1; o < 32; o <<= 1) {
                int t = __shfl_up_sync(FULLM, y, o);
                if (lane >= o) y += t;
            }
            s_wtot[lane] = y - w;
            if (lane == 31) s_wtot[32] = y;
        }
        __syncthreads();
        int excl = s_carry + s_wtot[wid] + (x - t3);
        if (i4 < N4) {
            int4 r;
            r.x = excl; r.y = excl + t0; r.z = excl + t1; r.w = excl + t2;
            rp4[i4] = r;
            cw4[i4] = r;
        }
        int btot = s_wtot[32];
        __syncthreads();
        if (tid == 0) s_carry += btot;
        __syncthreads();
    }
    if (tid == 0) g_rowptr[NN] = s_carry;
}

// ---------------- transform / alpha device functions ------------------------
#define TILES 16
template <int DIN, int DOUT, int STRIDE>
__device__ __forceinline__ void dev_transform(float* s_buf, int blk,
                                              const float* __restrict__ W) {
    constexpr int HD = 6 * DOUT;
    constexpr int C4 = HD / 4;
    constexpr int C4S = STRIDE / 4;
    constexpr int TOT = (NN / 4) * C4S;
    for (int i = threadIdx.x; i < DIN * HD; i += 256) {
        int k = i / DIN, d = i - k * DIN;
        s_buf[d * HD + k] = W[i];
    }
    __syncthreads();
    #pragma unroll
    for (int rep = 0; rep < TILES; rep++) {
        int t = (blk * TILES + rep) * 256 + threadIdx.x;
        if (t >= TOT) return;
        int c4 = t % C4S, nb = t / C4S;
        int n0 = nb * 4;
        float4 acc0 = {0,0,0,0}, acc1 = {0,0,0,0}, acc2 = {0,0,0,0}, acc3 = {0,0,0,0};
        if (c4 < C4) {
            const float4* x4 = g_hin4;
            const float4* w4 = reinterpret_cast<const float4*>(s_buf);
            #pragma unroll
            for (int dc = 0; dc < DIN / 4; dc++) {
                float4 xv0 = x4[(n0 + 0) * (DIN / 4) + dc];
                float4 xv1 = x4[(n0 + 1) * (DIN / 4) + dc];
                float4 xv2 = x4[(n0 + 2) * (DIN / 4) + dc];
                float4 xv3 = x4[(n0 + 3) * (DIN / 4) + dc];
                #pragma unroll
                for (int j = 0; j < 4; j++) {
                    float4 wv = w4[(dc * 4 + j) * C4 + c4];
                    fma4(acc0, wv, f4c(xv0, j));
                    fma4(acc1, wv, f4c(xv1, j));
                    fma4(acc2, wv, f4c(xv2, j));
                    fma4(acc3, wv, f4c(xv3, j));
                }
            }
        }
        __half* hb = g_hh;
        *reinterpret_cast<uint2*>(hb + (size_t)(n0 + 0) * STRIDE + c4 * 4) = f4_to_h4(acc0);
        *reinterpret_cast<uint2*>(hb + (size_t)(n0 + 1) * STRIDE + c4 * 4) = f4_to_h4(acc1);
        *reinterpret_cast<uint2*>(hb + (size_t)(n0 + 2) * STRIDE + c4 * 4) = f4_to_h4(acc2);
        *reinterpret_cast<uint2*>(hb + (size_t)(n0 + 3) * STRIDE + c4 * 4) = f4_to_h4(acc3);
    }
}

template <int DIN, int LAYER>
__device__ __forceinline__ void dev_alpha(float* s_buf, int blk) {
    for (int i = threadIdx.x; i < DIN * 12; i += 256)
        s_buf[i] = g_wa[LAYER * 384 + i];
    __syncthreads();
    #pragma unroll
    for (int rep = 0; rep < TILES; rep++) {
        int t2 = (blk * TILES + rep) * 256 + threadIdx.x;
        if (t2 >= NN * 12) return;
        int n = t2 / 12, hh = t2 - n * 12;
        const float4* xr4 = g_hin4 + (size_t)n * (DIN / 4);
        float acc = 0.f;
        #pragma unroll
        for (int d4 = 0; d4 < DIN / 4; d4++) {
            float4 xv = xr4[d4];
            acc += xv.x * s_buf[(d4 * 4 + 0) * 12 + hh]
                 + xv.y * s_buf[(d4 * 4 + 1) * 12 + hh]
                 + xv.z * s_buf[(d4 * 4 + 2) * 12 + hh]
                 + xv.w * s_buf[(d4 * 4 + 3) * 12 + hh];
        }
        reinterpret_cast<float*>(g_ae4)[n * 16 + (hh < 6 ? hh : hh + 2)] = acc;
    }
}

#define NBA2 CDIV(CDIV(NN * 12, 256), TILES)

// ---------------- launch 2: scatter + feat layer 1, fused -------------------
#define NBT1 CDIV(CDIV((NN / 4) * 48, 256), TILES)
#define SCAT_BLOCKS CDIV(ET, 256)
__global__ __launch_bounds__(256) void k_scatter_feat1(const int* __restrict__ ei,
                                                       const float* __restrict__ W) {
    __shared__ float s_buf[16 * 192];
    if (blockIdx.x < SCAT_BLOCKS) {
        int i = blockIdx.x * 256 + threadIdx.x;
        if (i >= ET) return;
        int s, d;
        if (i < EE) { s = ei[i]; d = ei[EE + i]; }
        else        { s = d = i - EE; }
        int pos = atomicAdd(&g_cursor[d], 1);
        g_csr[pos] = s;
    } else if (blockIdx.x < SCAT_BLOCKS + NBT1) {
        dev_transform<16, 32, 192>(s_buf, blockIdx.x - SCAT_BLOCKS, W);
    } else {
        dev_alpha<16, 0>(s_buf, blockIdx.x - SCAT_BLOCKS - NBT1);
    }
}

// ---------------- per-layer feat (layers 2-4) -------------------------------
template <int DIN, int DOUT, int STRIDE, int LAYER, bool ZERO_CURSOR>
__global__ __launch_bounds__(256) void k_feat(const float* __restrict__ W) {
    __shared__ float s_buf[DIN * 6 * DOUT];
    constexpr int NBT = CDIV(CDIV((NN / 4) * (STRIDE / 4), 256), TILES);
    if (blockIdx.x < NBT) {
        dev_transform<DIN, DOUT, STRIDE>(s_buf, blockIdx.x, W);
    } else if (blockIdx.x < NBT + NBA2) {
        dev_alpha<DIN, LAYER>(s_buf, blockIdx.x - NBT);
    } else if (ZERO_CURSOR) {
        int i = (blockIdx.x - NBT - NBA2) * 256 + threadIdx.x;
        if (i < NN) g_cursor[i] = 0;
    }
}

// ---------------- fused GAT (R10 proven variant) -----------------------------
template <int DOUT>
__global__ __launch_bounds__(256) void k_gat(const float* __restrict__ bias,
                                             float* __restrict__ out) {
    __shared__ float s_red[(DOUT > 2) ? 8 * 216 : 8];
    int w = threadIdx.x >> 5, lane = threadIdx.x & 31;
    int n = blockIdx.x * 8 + w;           // grid = NN/8 exactly
    int start = g_rowptr[n], end = g_rowptr[n + 1];
    int deg = end - start;

    const float4* ae4 = g_ae4;
    const float*  aef = reinterpret_cast<const float*>(g_ae4);
    float4 d03 = ae4[n * 4 + 2];
    float4 d45 = ae4[n * 4 + 3];
    float adh[6] = {d03.x, d03.y, d03.z, d03.w, d45.x, d45.y};
    float* sw = s_red + ((DOUT > 2) ? w * 216 : 0);
    const uint4* gh = reinterpret_cast<const uint4*>(g_hh);

    // ================= DOUT == 2 (HD=12, stride 16 halves) =================
    if constexpr (DOUT == 2) {
        float acc[12];
        #pragma unroll
        for (int k = 0; k < 12; k++) acc[k] = 0.f;
        if (deg <= 32) {
            int s = 0; bool act = lane < deg;
            if (act) s = g_csr[start + lane];
            float p[6], S[6];
            if (act) {
                float4 a03 = ae4[s * 4 + 0], a45 = ae4[s * 4 + 1];
                p[0] = __expf(lrelu(a03.x + adh[0]));
                p[1] = __expf(lrelu(a03.y + adh[1]));
                p[2] = __expf(lrelu(a03.z + adh[2]));
                p[3] = __expf(lrelu(a03.w + adh[3]));
                p[4] = __expf(lrelu(a45.x + adh[4]));
                p[5] = __expf(lrelu(a45.y + adh[5]));
            } else {
                #pragma unroll
                for (int h = 0; h < 6; h++) p[h] = 0.f;
            }
            #pragma unroll
            for (int h = 0; h < 6; h++) S[h] = p[h];
            #pragma unroll
            for (int h = 0; h < 6; h++)
                #pragma unroll
                for (int o = 16; o > 0; o >>= 1)
                    S[h] += __shfl_xor_sync(FULLM, S[h], o);
            float al[6];
            #pragma unroll
            for (int h = 0; h < 6; h++) al[h] = p[h] * (1.f / S[h]);
            if (act) {
                const uint4* hp = gh + s * 2;
                uint4 u0 = hp[0], u1 = hp[1];
                float2 f;
                f = __half22float2(u2h(u0.x)); acc[0] = f.x * al[0]; acc[1] = f.y * al[0];
                f = __half22float2(u2h(u0.y)); acc[2] = f.x * al[1]; acc[3] = f.y * al[1];
                f = __half22float2(u2h(u0.z)); acc[4] = f.x * al[2]; acc[5] = f.y * al[2];
                f = __half22float2(u2h(u0.w)); acc[6] = f.x * al[3]; acc[7] = f.y * al[3];
                f = __half22float2(u2h(u1.x)); acc[8] = f.x * al[4]; acc[9] = f.y * al[4];
                f = __half22float2(u2h(u1.y)); acc[10] = f.x * al[5]; acc[11] = f.y * al[5];
            }
        } else {
            float S[6];
            #pragma unroll
            for (int h = 0; h < 6; h++) S[h] = 0.f;
            for (int j = start + lane; j < end; j += 32) {
                int s = g_csr[j];
                float4 a03 = ae4[s * 4 + 0], a45 = ae4[s * 4 + 1];
                S[0] += __expf(lrelu(a03.x + adh[0]));
                S[1] += __expf(lrelu(a03.y + adh[1]));
                S[2] += __expf(lrelu(a03.z + adh[2]));
                S[3] += __expf(lrelu(a03.w + adh[3]));
                S[4] += __expf(lrelu(a45.x + adh[4]));
                S[5] += __expf(lrelu(a45.y + adh[5]));
            }
            #pragma unroll
            for (int h = 0; h < 6; h++)
                #pragma unroll
                for (int o = 16; o > 0; o >>= 1)
                    S[h] += __shfl_xor_sync(FULLM, S[h], o);
            float inv[6];
            #pragma unroll
            for (int h = 0; h < 6; h++) inv[h] = 1.f / S[h];
            for (int j = start + lane; j < end; j += 32) {
                int s = g_csr[j];
                float4 a03 = ae4[s * 4 + 0], a45 = ae4[s * 4 + 1];
                float al[6];
                al[0] = __expf(lrelu(a03.x + adh[0])) * inv[0];
                al[1] = __expf(lrelu(a03.y + adh[1])) * inv[1];
                al[2] = __expf(lrelu(a03.z + adh[2])) * inv[2];
                al[3] = __expf(lrelu(a03.w + adh[3])) * inv[3];
                al[4] = __expf(lrelu(a45.x + adh[4])) * inv[4];
                al[5] = __expf(lrelu(a45.y + adh[5])) * inv[5];
                const uint4* hp = gh + s * 2;
                uint4 u0 = hp[0], u1 = hp[1];
                float2 f;
                f = __half22float2(u2h(u0.x)); acc[0] += f.x * al[0]; acc[1] += f.y * al[0];
                f = __half22float2(u2h(u0.y)); acc[2] += f.x * al[1]; acc[3] += f.y * al[1];
                f = __half22float2(u2h(u0.z)); acc[4] += f.x * al[2]; acc[5] += f.y * al[2];
                f = __half22float2(u2h(u0.w)); acc[6] += f.x * al[3]; acc[7] += f.y * al[3];
                f = __half22float2(u2h(u1.x)); acc[8] += f.x * al[4]; acc[9] += f.y * al[4];
                f = __half22float2(u2h(u1.y)); acc[10] += f.x * al[5]; acc[11] += f.y * al[5];
            }
        }
        float q0 = acc[0] + acc[2] + acc[4] + acc[6] + acc[8] + acc[10];
        float q1 = acc[1] + acc[3] + acc[5] + acc[7] + acc[9] + acc[11];
        #pragma unroll
        for (int o = 16; o > 0; o >>= 1) {
            q0 += __shfl_xor_sync(FULLM, q0, o);
            q1 += __shfl_xor_sync(FULLM, q1, o);
        }
        if (lane < 2) {
            float v = lane ? q1 : q0;
            out[n * 2 + lane] = selu_f(v * (1.f / 6.f) + bias[lane]);
        }
        return;
    }

    // ================= DOUT == 32 / 16 =================
    bool actl = lane < 24;
    int hidx, ll = 0, eo = 0;
    if constexpr (DOUT == 32) {
        hidx = actl ? (lane >> 2) : 0;
    } else {
        ll = actl ? (lane % 12) : 0;
        eo = actl ? (lane / 12) : 0;
        hidx = ll >> 1;
    }
    constexpr int NU4 = (DOUT == 32) ? 24 : 12;   // uint4 per node row
    float f[8];
    #pragma unroll
    for (int k = 0; k < 8; k++) f[k] = 0.f;
    unsigned* swu = reinterpret_cast<unsigned*>(sw);

    if (deg <= 32) {
        // ---- fast path: lane-per-edge softmax (no max shift) ----
        int s = 0; bool act = lane < deg;
        if (act) s = g_csr[start + lane];
        float p[6], S[6];
        if (act) {
            float4 a03 = ae4[s * 4 + 0], a45 = ae4[s * 4 + 1];
            p[0] = __expf(lrelu(a03.x + adh[0]));
            p[1] = __expf(lrelu(a03.y + adh[1]));
            p[2] = __expf(lrelu(a03.z + adh[2]));
            p[3] = __expf(lrelu(a03.w + adh[3]));
            p[4] = __expf(lrelu(a45.x + adh[4]));
            p[5] = __expf(lrelu(a45.y + adh[5]));
        } else {
            #pragma unroll
            for (int h = 0; h < 6; h++) p[h] = 0.f;
        }
        #pragma unroll
        for (int h = 0; h < 6; h++) S[h] = p[h];
        #pragma unroll
        for (int h = 0; h < 6; h++)
            #pragma unroll
            for (int o = 16; o > 0; o >>= 1)
                S[h] += __shfl_xor_sync(FULLM, S[h], o);
        // stage normalized alphas as broadcast half2, head-major stride 36
        #pragma unroll
        for (int h = 0; h < 6; h++) {
            __half2 ah = __float2half2_rn(p[h] * (1.f / S[h]));
            swu[h * 36 + lane] = *reinterpret_cast<unsigned*>(&ah);
        }
        __syncwarp();

        int degR = (deg + 3) & ~3;       // padded edges have alpha=0, s=0 (valid row)

        if constexpr (DOUT == 32) {
            for (int j = 0; j < degR; j += 4) {
                int s0 = __shfl_sync(FULLM, s, j);
                int s1 = __shfl_sync(FULLM, s, j + 1);
                int s2 = __shfl_sync(FULLM, s, j + 2);
                int s3 = __shfl_sync(FULLM, s, j + 3);
                uint4 au = *reinterpret_cast<const uint4*>(&swu[hidx * 36 + j]);
                __half2 a0 = u2h(au.x), a1 = u2h(au.y), a2 = u2h(au.z), a3 = u2h(au.w);
                uint4 v0 = {0,0,0,0}, v1 = {0,0,0,0}, v2 = {0,0,0,0}, v3 = {0,0,0,0};
                if (actl) {
                    v0 = gh[(size_t)s0 * NU4 + lane];
                    v1 = gh[(size_t)s1 * NU4 + lane];
                    v2 = gh[(size_t)s2 * NU4 + lane];
                    v3 = gh[(size_t)s3 * NU4 + lane];
                }
                __half2 g0 = __hmul2(u2h(v0.x), a0);
                __half2 g1 = __hmul2(u2h(v0.y), a0);
                __half2 g2 = __hmul2(u2h(v0.z), a0);
                __half2 g3 = __hmul2(u2h(v0.w), a0);
                g0 = __hfma2(u2h(v1.x), a1, g0);
                g1 = __hfma2(u2h(v1.y), a1, g1);
                g2 = __hfma2(u2h(v1.z), a1, g2);
                g3 = __hfma2(u2h(v1.w), a1, g3);
                g0 = __hfma2(u2h(v2.x), a2, g0);
                g1 = __hfma2(u2h(v2.y), a2, g1);
                g2 = __hfma2(u2h(v2.z), a2, g2);
                g3 = __hfma2(u2h(v2.w), a2, g3);
                g0 = __hfma2(u2h(v3.x), a3, g0);
                g1 = __hfma2(u2h(v3.y), a3, g1);
                g2 = __hfma2(u2h(v3.z), a3, g2);
                g3 = __hfma2(u2h(v3.w), a3, g3);
                float2 t;
                t = __half22float2(g0); f[0] += t.x; f[1] += t.y;
                t = __half22float2(g1); f[2] += t.x; f[3] += t.y;
                t = __half22float2(g2); f[4] += t.x; f[5] += t.y;
                t = __half22float2(g3); f[6] += t.x; f[7] += t.y;
            }
        } else { // DOUT == 16: 4 edges per iter (2 per eo group)
            for (int j = 0; j < degR; j += 4) {
                int js0 = j + eo, js1 = j + 2 + eo;
                int t0 = __shfl_sync(FULLM, s, js0);
                int t1 = __shfl_sync(FULLM, s, js1);
                __half2 a0 = u2h(actl ? swu[hidx * 36 + js0] : 0u);
                __half2 a1 = u2h(actl ? swu[hidx * 36 + js1] : 0u);
                uint4 v0 = {0,0,0,0}, v1 = {0,0,0,0};
                if (actl) {
                    v0 = gh[(size_t)t0 * NU4 + ll];
                    v1 = gh[(size_t)t1 * NU4 + ll];
                }
                __half2 g0 = __hmul2(u2h(v0.x), a0);
                __half2 g1 = __hmul2(u2h(v0.y), a0);
                __half2 g2 = __hmul2(u2h(v0.z), a0);
                __half2 g3 = __hmul2(u2h(v0.w), a0);
                g0 = __hfma2(u2h(v1.x), a1, g0);
                g1 = __hfma2(u2h(v1.y), a1, g1);
                g2 = __hfma2(u2h(v1.z), a1, g2);
                g3 = __hfma2(u2h(v1.w), a1, g3);
                float2 t;
                t = __half22float2(g0); f[0] += t.x; f[1] += t.y;
                t = __half22float2(g1); f[2] += t.x; f[3] += t.y;
                t = __half22float2(g2); f[4] += t.x; f[5] += t.y;
                t = __half22float2(g3); f[6] += t.x; f[7] += t.y;
            }
        }
    } else {
        // ---- slow path (deg > 32, rare): fp32 math ----
        float S[6];
        #pragma unroll
        for (int h = 0; h < 6; h++) S[h] = 0.f;
        for (int j = start + lane; j < end; j += 32) {
            int s = g_csr[j];
            float4 a03 = ae4[s * 4 + 0], a45 = ae4[s * 4 + 1];
            S[0] += __expf(lrelu(a03.x + adh[0]));
            S[1] += __expf(lrelu(a03.y + adh[1]));
            S[2] += __expf(lrelu(a03.z + adh[2]));
            S[3] += __expf(lrelu(a03.w + adh[3]));
            S[4] += __expf(lrelu(a45.x + adh[4]));
            S[5] += __expf(lrelu(a45.y + adh[5]));
        }
        #pragma unroll
        for (int h = 0; h < 6; h++)
            #pragma unroll
            for (int o = 16; o > 0; o >>= 1)
                S[h] += __shfl_xor_sync(FULLM, S[h], o);
        float inv_sel = 0.f, ad_sel = 0.f;
        #pragma unroll
        for (int h = 0; h < 6; h++)
            if (hidx == h) { inv_sel = 1.f / S[h]; ad_sel = adh[h]; }

        bool act_agg = (DOUT == 32) ? actl : (actl && eo == 0);
        int dlane = (DOUT == 32) ? lane : ll;
        for (int j = start; j < end; j++) {
            int s0 = g_csr[j];
            float a = 0.f;
            uint4 v = {0,0,0,0};
            if (act_agg) {
                float e = lrelu(aef[s0 * 16 + hidx] + ad_sel);
                a = __expf(e) * inv_sel;
                v = gh[(size_t)s0 * NU4 + dlane];
            }
            float2 t;
            t = __half22float2(u2h(v.x)); f[0] += t.x * a; f[1] += t.y * a;
            t = __half22float2(u2h(v.y)); f[2] += t.x * a; f[3] += t.y * a;
            t = __half22float2(u2h(v.z)); f[4] += t.x * a; f[5] += t.y * a;
            t = __half22float2(u2h(v.w)); f[6] += t.x * a; f[7] += t.y * a;
        }
    }

    // ---- common epilogue: smem transpose, head mean + bias + SELU ----
    __syncwarp();
    if constexpr (DOUT == 32) {
        if (actl) {
            int b = lane * 8;
            #pragma unroll
            for (int k = 0; k < 8; k++) sw[b + k] = f[k];
        }
        __syncwarp();
        float o0 = sw[lane] + sw[32 + lane] + sw[64 + lane] +
                   sw[96 + lane] + sw[128 + lane] + sw[160 + lane];
        out[n * 32 + lane] = selu_f(o0 * (1.f / 6.f) + bias[lane]);
    } else {
        if (actl) {
            int b = eo * 96 + ll * 8;
            #pragma unroll
            for (int k = 0; k < 8; k++) sw[b + k] = f[k];
        }
        __syncwarp();
        if (lane < 16) {
            float o0 = 0.f;
            #pragma unroll
            for (int h = 0; h < 6; h++)
                o0 += sw[h * 16 + lane] + sw[96 + h * 16 + lane];
            out[n * 16 + lane] = selu_f(o0 * (1.f / 6.f) + bias[lane]);
        }
    }
}

// ---------------- host launcher ---------------------------------------------
extern "C" void kernel_launch(void* const* d_in, const int* in_sizes, int n_in,
                              void* d_out, int out_size) {
    (void)in_sizes; (void)n_in; (void)out_size;
    const float* x     = (const float*)d_in[0];
    const int*   ei    = (const int*)d_in[1];
    const float* lin_w = (const float*)d_in[2];
    const float* lin_b = (const float*)d_in[3];
    const float* W[4]  = { (const float*)d_in[4],  (const float*)d_in[8],
                           (const float*)d_in[12], (const float*)d_in[16] };
    const float* AS[4] = { (const float*)d_in[5],  (const float*)d_in[9],
                           (const float*)d_in[13], (const float*)d_in[17] };
    const float* AD[4] = { (const float*)d_in[6],  (const float*)d_in[10],
                           (const float*)d_in[14], (const float*)d_in[18] };
    const float* B[4]  = { (const float*)d_in[7],  (const float*)d_in[11],
                           (const float*)d_in[15], (const float*)d_in[19] };
    float* out = (float*)d_out;

    float* g_hin_ptr = nullptr;
    cudaGetSymbolAddress((void**)&g_hin_ptr, g_hin4);

    const int gat_blocks = NN / 8;

    // 0: count + lin0 + wa
    k_count_lin0<<<CNT_BLOCKS + LIN0_BLOCKS + 1, 256>>>(
        ei, x, lin_w, lin_b,
        W[0], AS[0], AD[0], W[1], AS[1], AD[1],
        W[2], AS[2], AD[2], W[3], AS[3], AD[3]);
    // 1: scan
    k_scan<<<1, 1024>>>();
    // 2: scatter + feat layer 1 (fused, independent block ranges)
    k_scatter_feat1<<<SCAT_BLOCKS + NBT1 + NBA2, 256>>>(ei, W[0]);
    // 3: gat layer 1   <- ncu capture target
    k_gat<32><<<gat_blocks, 256>>>(B[0], g_hin_ptr);
    // 4-5: layer 2
    {
        constexpr int nbt = CDIV(CDIV((NN / 4) * 48, 256), TILES);
        k_feat<32, 32, 192, 1, false><<<nbt + NBA2, 256>>>(W[1]);
    }
    k_gat<32><<<gat_blocks, 256>>>(B[1], g_hin_ptr);
    // 6-7: layer 3
    {
        constexpr int nbt = CDIV(CDIV((NN / 4) * 24, 256), TILES);
        k_feat<32, 16, 96, 2, false><<<nbt + NBA2, 256>>>(W[2]);
    }
    k_gat<16><<<gat_blocks, 256>>>(B[2], g_hin_ptr);
    // 8-9: layer 4 (+cursor re-zero for next call)
    {
        constexpr int nbt = CDIV(CDIV((NN / 4) * 4, 256), TILES);
        k_feat<16, 2, 16, 3, true><<<nbt + NBA2 + CDIV(NN, 256), 256>>>(W[3]);
    }
    k_gat<2><<<gat_blocks, 256>>>(B[3], out);
}

// round 15
// speedup vs baseline: 1.0312x; 1.0301x over previous
#include <cuda_runtime.h>
#include <cuda_fp16.h>

#define NN 50000
#define EE 800000
#define ET (EE + NN)   // edges + self loops
#define FULLM 0xffffffffu

__host__ __device__ constexpr int CDIV(int a, int b) { return (a + b - 1) / b; }

// ---------------- scratch (static __device__ globals; no allocs) -------------
__device__ __align__(16) int g_rowptr[NN + 4];
__device__ __align__(16) int g_cursor[NN];       // zero at call start (invariant)
__device__ int    g_csr[ET];
__device__ float4 g_hin4[NN * 8];        // node features [n][din] fp32, din<=32
__device__ __align__(128) __half g_hh[NN * 192];  // transformed features, fp16
__device__ float4 g_ae4[NN * 4];         // [n][16]: 0..5 src logits, 8..13 dst logits
__device__ float  g_wa[4 * 384];         // folded attention mats: [l][d*12+hh]

__device__ __forceinline__ float selu_f(float x) {
    const float sc = 1.0507009873554805f;
    const float al = 1.6732632423543772f;
    return x > 0.f ? sc * x : sc * al * (__expf(x) - 1.f);
}
__device__ __forceinline__ float lrelu(float x) { return x > 0.f ? x : 0.2f * x; }
__device__ __forceinline__ float f4c(const float4& v, int j) {
    return j == 0 ? v.x : j == 1 ? v.y : j == 2 ? v.z : v.w;
}
__device__ __forceinline__ void fma4(float4& a, const float4& v, float s) {
    a.x += v.x * s; a.y += v.y * s; a.z += v.z * s; a.w += v.w * s;
}
__device__ __forceinline__ uint2 f4_to_h4(float4 a) {
    __half2 lo = __floats2half2_rn(a.x, a.y);
    __half2 hi = __floats2half2_rn(a.z, a.w);
    uint2 r;
    r.x = *reinterpret_cast<unsigned*>(&lo);
    r.y = *reinterpret_cast<unsigned*>(&hi);
    return r;
}
__device__ __forceinline__ __half2 u2h(unsigned u) {
    return *reinterpret_cast<__half2*>(&u);
}

// ---------------- launch 0: count + lin0 + wa precompute --------------------
#define CNT_BLOCKS  CDIV(EE, 256)
#define LIN0_BLOCKS CDIV(NN * 16, 256)
__global__ __launch_bounds__(256) void k_count_lin0(
    const int* __restrict__ ei, const float* __restrict__ x,
    const float* __restrict__ lw, const float* __restrict__ lb,
    const float* __restrict__ W1, const float* __restrict__ AS1, const float* __restrict__ AD1,
    const float* __restrict__ W2, const float* __restrict__ AS2, const float* __restrict__ AD2,
    const float* __restrict__ W3, const float* __restrict__ AS3, const float* __restrict__ AD3,
    const float* __restrict__ W4, const float* __restrict__ AS4, const float* __restrict__ AD4) {
    if (blockIdx.x < CNT_BLOCKS) {
        int i = blockIdx.x * 256 + threadIdx.x;
        if (i < EE) atomicAdd(&g_cursor[ei[EE + i]], 1);
    } else if (blockIdx.x < CNT_BLOCKS + LIN0_BLOCKS) {
        int i = (blockIdx.x - CNT_BLOCKS) * 256 + threadIdx.x;
        if (i >= NN * 16) return;
        int n = i >> 4, c = i & 15;
        const float* xr = x + n * 10;
        const float* wr = lw + c * 10;
        float acc = lb[c];
        #pragma unroll
        for (int d = 0; d < 10; d++) acc += xr[d] * wr[d];
        reinterpret_cast<float*>(g_hin4)[i] = selu_f(acc);
    } else {
        const float* Ws[4]  = {W1, W2, W3, W4};
        const float* ASs[4] = {AS1, AS2, AS3, AS4};
        const float* ADs[4] = {AD1, AD2, AD3, AD4};
        const int din[4]  = {16, 32, 32, 16};
        const int dout[4] = {32, 32, 16, 2};
        for (int e = threadIdx.x; e < 4 * 384; e += 256) {
            int l = e / 384, r = e - l * 384, d = r / 12, hh = r - d * 12;
            if (d >= din[l]) continue;
            int head = hh % 6;
            int DO = dout[l], DI = din[l];
            const float* av = (hh < 6 ? ASs[l] : ADs[l]) + head * DO;
            const float* Wl = Ws[l];
            float s = 0.f;
            for (int o = 0; o < DO; o++) s += av[o] * Wl[(head * DO + o) * DI + d];
            g_wa[e] = s;
        }
    }
}

// ---------------- launch 1: scan, 4 elems/thread (adds self-loop +1) --------
__global__ void k_scan() {
    __shared__ int s_wtot[33];
    __shared__ int s_carry;
    int tid = threadIdx.x, lane = tid & 31, wid = tid >> 5;
    if (tid == 0) s_carry = 0;
    __syncthreads();
    const int4* cur4 = reinterpret_cast<const int4*>(g_cursor);
    int4* cw4 = reinterpret_cast<int4*>(g_cursor);
    int4* rp4 = reinterpret_cast<int4*>(g_rowptr);
    constexpr int N4 = NN / 4;       // 12500
    for (int base = 0; base < N4; base += 1024) {
        int i4 = base + tid;
        int4 v = {0, 0, 0, 0};
        if (i4 < N4) {
            v = cur4[i4];
            v.x++; v.y++; v.z++; v.w++;   // self loops
        }
        int t0 = v.x, t1 = t0 + v.y, t2 = t1 + v.z, t3 = t2 + v.w;
        int x = t3;
        #pragma unroll
        for (int o = 1; o < 32; o <<= 1) {
            int t = __shfl_up_sync(FULLM, x, o);
            if (lane >= o) x += t;
        }
        if (lane == 31) s_wtot[wid] = x;
        __syncthreads();
        if (wid == 0) {
            int w = s_wtot[lane];
            int y = w;
            #pragma unroll
            for (int o = 1; o < 32; o <<= 1) {
                int t = __shfl_up_sync(FULLM, y, o);
                if (lane >= o) y += t;
            }
            s_wtot[lane] = y - w;
            if (lane == 31) s_wtot[32] = y;
        }
        __syncthreads();
        int excl = s_carry + s_wtot[wid] + (x - t3);
        if (i4 < N4) {
            int4 r;
            r.x = excl; r.y = excl + t0; r.z = excl + t1; r.w = excl + t2;
            rp4[i4] = r;
            cw4[i4] = r;
        }
        int btot = s_wtot[32];
        __syncthreads();
        if (tid == 0) s_carry += btot;
        __syncthreads();
    }
    if (tid == 0) g_rowptr[NN] = s_carry;
}

// ---------------- node-per-thread transform + alpha --------------------------
// x in registers; W staged [d][HD] in smem, read with warp-uniform broadcast.
template <int DIN, int DOUT, int STRIDE, int LAYER>
__device__ __forceinline__ void dev_feat_node(float* s_w, float* s_wa, int blk,
                                              const float* __restrict__ W) {
    constexpr int HD = 6 * DOUT;
    constexpr int C4 = HD / 4;
    for (int i = threadIdx.x; i < DIN * HD; i += 256) {
        int k = i / DIN, d = i - k * DIN;
        s_w[d * HD + k] = W[i];
    }
    for (int i = threadIdx.x; i < DIN * 12; i += 256)
        s_wa[i] = g_wa[LAYER * 384 + i];
    __syncthreads();

    int n = blk * 256 + threadIdx.x;
    if (n >= NN) return;

    float4 xv[DIN / 4];
    const float4* xr = g_hin4 + (size_t)n * (DIN / 4);
    #pragma unroll
    for (int d4 = 0; d4 < DIN / 4; d4++) xv[d4] = xr[d4];

    const float4* w4 = reinterpret_cast<const float4*>(s_w);  // [d][C4]
    __half* hb = g_hh + (size_t)n * STRIDE;

    for (int c4 = 0; c4 < C4; c4++) {          // uniform across warp -> broadcast LDS
        float4 acc = {0.f, 0.f, 0.f, 0.f};
        #pragma unroll
        for (int d4 = 0; d4 < DIN / 4; d4++) {
            #pragma unroll
            for (int j = 0; j < 4; j++)
                fma4(acc, w4[(d4 * 4 + j) * C4 + c4], f4c(xv[d4], j));
        }
        *reinterpret_cast<uint2*>(hb + c4 * 4) = f4_to_h4(acc);
    }
    #pragma unroll
    for (int c4 = C4; c4 < STRIDE / 4; c4++) { // zero pad (layer 4 only)
        uint2 z; z.x = 0u; z.y = 0u;
        *reinterpret_cast<uint2*>(hb + c4 * 4) = z;
    }

    // alpha logits from the same x registers
    float* aeout = reinterpret_cast<float*>(g_ae4) + (size_t)n * 16;
    #pragma unroll
    for (int hh = 0; hh < 12; hh++) {
        float a = 0.f;
        #pragma unroll
        for (int d4 = 0; d4 < DIN / 4; d4++) {
            #pragma unroll
            for (int j = 0; j < 4; j++)
                a += f4c(xv[d4], j) * s_wa[(d4 * 4 + j) * 12 + hh];
        }
        aeout[hh < 6 ? hh : hh + 2] = a;
    }
}

#define FEAT_BLOCKS CDIV(NN, 256)

// ---------------- launch 2: scatter + feat layer 1, fused -------------------
#define SCAT_BLOCKS CDIV(ET, 256)
__global__ __launch_bounds__(256) void k_scatter_feat1(const int* __restrict__ ei,
                                                       const float* __restrict__ W) {
    __shared__ float s_w[16 * 192];
    __shared__ float s_wa[16 * 12];
    if (blockIdx.x < SCAT_BLOCKS) {
        int i = blockIdx.x * 256 + threadIdx.x;
        if (i >= ET) return;
        int s, d;
        if (i < EE) { s = ei[i]; d = ei[EE + i]; }
        else        { s = d = i - EE; }
        int pos = atomicAdd(&g_cursor[d], 1);
        g_csr[pos] = s;
    } else {
        dev_feat_node<16, 32, 192, 0>(s_w, s_wa, blockIdx.x - SCAT_BLOCKS, W);
    }
}

// ---------------- per-layer feat (layers 2-4) -------------------------------
template <int DIN, int DOUT, int STRIDE, int LAYER, bool ZERO_CURSOR>
__global__ __launch_bounds__(256) void k_feat(const float* __restrict__ W) {
    __shared__ float s_w[DIN * 6 * DOUT];
    __shared__ float s_wa[DIN * 12];
    if (blockIdx.x < FEAT_BLOCKS) {
        dev_feat_node<DIN, DOUT, STRIDE, LAYER>(s_w, s_wa, blockIdx.x, W);
    } else if (ZERO_CURSOR) {
        int i = (blockIdx.x - FEAT_BLOCKS) * 256 + threadIdx.x;
        if (i < NN) g_cursor[i] = 0;
    }
}

// ---------------- fused GAT (proven 52-us variant) ---------------------------
template <int DOUT>
__global__ __launch_bounds__(256) void k_gat(const float* __restrict__ bias,
                                             float* __restrict__ out) {
    __shared__ float s_red[(DOUT > 2) ? 8 * 216 : 8];
    int w = threadIdx.x >> 5, lane = threadIdx.x & 31;
    int n = blockIdx.x * 8 + w;           // grid = NN/8 exactly
    int start = g_rowptr[n], end = g_rowptr[n + 1];
    int deg = end - start;

    const float4* ae4 = g_ae4;
    const float*  aef = reinterpret_cast<const float*>(g_ae4);
    float4 d03 = ae4[n * 4 + 2];
    float4 d45 = ae4[n * 4 + 3];
    float adh[6] = {d03.x, d03.y, d03.z, d03.w, d45.x, d45.y};
    float* sw = s_red + ((DOUT > 2) ? w * 216 : 0);
    const uint4* gh = reinterpret_cast<const uint4*>(g_hh);

    // ================= DOUT == 2 (HD=12, stride 16 halves) =================
    if constexpr (DOUT == 2) {
        float acc[12];
        #pragma unroll
        for (int k = 0; k < 12; k++) acc[k] = 0.f;
        if (deg <= 32) {
            int s = 0; bool act = lane < deg;
            if (act) s = g_csr[start + lane];
            float p[6], S[6];
            if (act) {
                float4 a03 = ae4[s * 4 + 0], a45 = ae4[s * 4 + 1];
                p[0] = __expf(lrelu(a03.x + adh[0]));
                p[1] = __expf(lrelu(a03.y + adh[1]));
                p[2] = __expf(lrelu(a03.z + adh[2]));
                p[3] = __expf(lrelu(a03.w + adh[3]));
                p[4] = __expf(lrelu(a45.x + adh[4]));
                p[5] = __expf(lrelu(a45.y + adh[5]));
            } else {
                #pragma unroll
                for (int h = 0; h < 6; h++) p[h] = 0.f;
            }
            #pragma unroll
            for (int h = 0; h < 6; h++) S[h] = p[h];
            #pragma unroll
            for (int h = 0; h < 6; h++)
                #pragma unroll
                for (int o = 16; o > 0; o >>= 1)
                    S[h] += __shfl_xor_sync(FULLM, S[h], o);
            float al[6];
            #pragma unroll
            for (int h = 0; h < 6; h++) al[h] = p[h] * (1.f / S[h]);
            if (act) {
                const uint4* hp = gh + s * 2;
                uint4 u0 = hp[0], u1 = hp[1];
                float2 f;
                f = __half22float2(u2h(u0.x)); acc[0] = f.x * al[0]; acc[1] = f.y * al[0];
                f = __half22float2(u2h(u0.y)); acc[2] = f.x * al[1]; acc[3] = f.y * al[1];
                f = __half22float2(u2h(u0.z)); acc[4] = f.x * al[2]; acc[5] = f.y * al[2];
                f = __half22float2(u2h(u0.w)); acc[6] = f.x * al[3]; acc[7] = f.y * al[3];
                f = __half22float2(u2h(u1.x)); acc[8] = f.x * al[4]; acc[9] = f.y * al[4];
                f = __half22float2(u2h(u1.y)); acc[10] = f.x * al[5]; acc[11] = f.y * al[5];
            }
        } else {
            float S[6];
            #pragma unroll
            for (int h = 0; h < 6; h++) S[h] = 0.f;
            for (int j = start + lane; j < end; j += 32) {
                int s = g_csr[j];
                float4 a03 = ae4[s * 4 + 0], a45 = ae4[s * 4 + 1];
                S[0] += __expf(lrelu(a03.x + adh[0]));
                S[1] += __expf(lrelu(a03.y + adh[1]));
                S[2] += __expf(lrelu(a03.z + adh[2]));
                S[3] += __expf(lrelu(a03.w + adh[3]));
                S[4] += __expf(lrelu(a45.x + adh[4]));
                S[5] += __expf(lrelu(a45.y + adh[5]));
            }
            #pragma unroll
            for (int h = 0; h < 6; h++)
                #pragma unroll
                for (int o = 16; o > 0; o >>= 1)
                    S[h] += __shfl_xor_sync(FULLM, S[h], o);
            float inv[6];
            #pragma unroll
            for (int h = 0; h < 6; h++) inv[h] = 1.f / S[h];
            for (int j = start + lane; j < end; j += 32) {
                int s = g_csr[j];
                float4 a03 = ae4[s * 4 + 0], a45 = ae4[s * 4 + 1];
                float al[6];
                al[0] = __expf(lrelu(a03.x + adh[0])) * inv[0];
                al[1] = __expf(lrelu(a03.y + adh[1])) * inv[1];
                al[2] = __expf(lrelu(a03.z + adh[2])) * inv[2];
                al[3] = __expf(lrelu(a03.w + adh[3])) * inv[3];
                al[4] = __expf(lrelu(a45.x + adh[4])) * inv[4];
                al[5] = __expf(lrelu(a45.y + adh[5])) * inv[5];
                const uint4* hp = gh + s * 2;
                uint4 u0 = hp[0], u1 = hp[1];
                float2 f;
                f = __half22float2(u2h(u0.x)); acc[0] += f.x * al[0]; acc[1] += f.y * al[0];
                f = __half22float2(u2h(u0.y)); acc[2] += f.x * al[1]; acc[3] += f.y * al[1];
                f = __half22float2(u2h(u0.z)); acc[4] += f.x * al[2]; acc[5] += f.y * al[2];
                f = __half22float2(u2h(u0.w)); acc[6] += f.x * al[3]; acc[7] += f.y * al[3];
                f = __half22float2(u2h(u1.x)); acc[8] += f.x * al[4]; acc[9] += f.y * al[4];
                f = __half22float2(u2h(u1.y)); acc[10] += f.x * al[5]; acc[11] += f.y * al[5];
            }
        }
        float q0 = acc[0] + acc[2] + acc[4] + acc[6] + acc[8] + acc[10];
        float q1 = acc[1] + acc[3] + acc[5] + acc[7] + acc[9] + acc[11];
        #pragma unroll
        for (int o = 16; o > 0; o >>= 1) {
            q0 += __shfl_xor_sync(FULLM, q0, o);
            q1 += __shfl_xor_sync(FULLM, q1, o);
        }
        if (lane < 2) {
            float v = lane ? q1 : q0;
            out[n * 2 + lane] = selu_f(v * (1.f / 6.f) + bias[lane]);
        }
        return;
    }

    // ================= DOUT == 32 / 16 =================
    bool actl = lane < 24;
    int hidx, ll = 0, eo = 0;
    if constexpr (DOUT == 32) {
        hidx = actl ? (lane >> 2) : 0;
    } else {
        ll = actl ? (lane % 12) : 0;
        eo = actl ? (lane / 12) : 0;
        hidx = ll >> 1;
    }
    constexpr int NU4 = (DOUT == 32) ? 24 : 12;   // uint4 per node row
    float f[8];
    #pragma unroll
    for (int k = 0; k < 8; k++) f[k] = 0.f;
    unsigned* swu = reinterpret_cast<unsigned*>(sw);

    if (deg <= 32) {
        // ---- fast path: lane-per-edge softmax (no max shift) ----
        int s = 0; bool act = lane < deg;
        if (act) s = g_csr[start + lane];
        float p[6], S[6];
        if (act) {
            float4 a03 = ae4[s * 4 + 0], a45 = ae4[s * 4 + 1];
            p[0] = __expf(lrelu(a03.x + adh[0]));
            p[1] = __expf(lrelu(a03.y + adh[1]));
            p[2] = __expf(lrelu(a03.z + adh[2]));
            p[3] = __expf(lrelu(a03.w + adh[3]));
            p[4] = __expf(lrelu(a45.x + adh[4]));
            p[5] = __expf(lrelu(a45.y + adh[5]));
        } else {
            #pragma unroll
            for (int h = 0; h < 6; h++) p[h] = 0.f;
        }
        #pragma unroll
        for (int h = 0; h < 6; h++) S[h] = p[h];
        #pragma unroll
        for (int h = 0; h < 6; h++)
            #pragma unroll
            for (int o = 16; o > 0; o >>= 1)
                S[h] += __shfl_xor_sync(FULLM, S[h], o);
        // stage normalized alphas as broadcast half2, head-major stride 36
        #pragma unroll
        for (int h = 0; h < 6; h++) {
            __half2 ah = __float2half2_rn(p[h] * (1.f / S[h]));
            swu[h * 36 + lane] = *reinterpret_cast<unsigned*>(&ah);
        }
        __syncwarp();

        int degR = (deg + 3) & ~3;       // padded edges have alpha=0, s=0 (valid row)

        if constexpr (DOUT == 32) {
            for (int j = 0; j < degR; j += 4) {
                int s0 = __shfl_sync(FULLM, s, j);
                int s1 = __shfl_sync(FULLM, s, j + 1);
                int s2 = __shfl_sync(FULLM, s, j + 2);
                int s3 = __shfl_sync(FULLM, s, j + 3);
                uint4 au = *reinterpret_cast<const uint4*>(&swu[hidx * 36 + j]);
                __half2 a0 = u2h(au.x), a1 = u2h(au.y), a2 = u2h(au.z), a3 = u2h(au.w);
                uint4 v0 = {0,0,0,0}, v1 = {0,0,0,0}, v2 = {0,0,0,0}, v3 = {0,0,0,0};
                if (actl) {
                    v0 = gh[(size_t)s0 * NU4 + lane];
                    v1 = gh[(size_t)s1 * NU4 + lane];
                    v2 = gh[(size_t)s2 * NU4 + lane];
                    v3 = gh[(size_t)s3 * NU4 + lane];
                }
                __half2 g0 = __hmul2(u2h(v0.x), a0);
                __half2 g1 = __hmul2(u2h(v0.y), a0);
                __half2 g2 = __hmul2(u2h(v0.z), a0);
                __half2 g3 = __hmul2(u2h(v0.w), a0);
                g0 = __hfma2(u2h(v1.x), a1, g0);
                g1 = __hfma2(u2h(v1.y), a1, g1);
                g2 = __hfma2(u2h(v1.z), a1, g2);
                g3 = __hfma2(u2h(v1.w), a1, g3);
                g0 = __hfma2(u2h(v2.x), a2, g0);
                g1 = __hfma2(u2h(v2.y), a2, g1);
                g2 = __hfma2(u2h(v2.z), a2, g2);
                g3 = __hfma2(u2h(v2.w), a2, g3);
                g0 = __hfma2(u2h(v3.x), a3, g0);
                g1 = __hfma2(u2h(v3.y), a3, g1);
                g2 = __hfma2(u2h(v3.z), a3, g2);
                g3 = __hfma2(u2h(v3.w), a3, g3);
                float2 t;
                t = __half22float2(g0); f[0] += t.x; f[1] += t.y;
                t = __half22float2(g1); f[2] += t.x; f[3] += t.y;
                t = __half22float2(g2); f[4] += t.x; f[5] += t.y;
                t = __half22float2(g3); f[6] += t.x; f[7] += t.y;
            }
        } else { // DOUT == 16: 4 edges per iter (2 per eo group)
            for (int j = 0; j < degR; j += 4) {
                int js0 = j + eo, js1 = j + 2 + eo;
                int t0 = __shfl_sync(FULLM, s, js0);
                int t1 = __shfl_sync(FULLM, s, js1);
                __half2 a0 = u2h(actl ? swu[hidx * 36 + js0] : 0u);
                __half2 a1 = u2h(actl ? swu[hidx * 36 + js1] : 0u);
                uint4 v0 = {0,0,0,0}, v1 = {0,0,0,0};
                if (actl) {
                    v0 = gh[(size_t)t0 * NU4 + ll];
                    v1 = gh[(size_t)t1 * NU4 + ll];
                }
                __half2 g0 = __hmul2(u2h(v0.x), a0);
                __half2 g1 = __hmul2(u2h(v0.y), a0);
                __half2 g2 = __hmul2(u2h(v0.z), a0);
                __half2 g3 = __hmul2(u2h(v0.w), a0);
                g0 = __hfma2(u2h(v1.x), a1, g0);
                g1 = __hfma2(u2h(v1.y), a1, g1);
                g2 = __hfma2(u2h(v1.z), a1, g2);
                g3 = __hfma2(u2h(v1.w), a1, g3);
                float2 t;
                t = __half22float2(g0); f[0] += t.x; f[1] += t.y;
                t = __half22float2(g1); f[2] += t.x; f[3] += t.y;
                t = __half22float2(g2); f[4] += t.x; f[5] += t.y;
                t = __half22float2(g3); f[6] += t.x; f[7] += t.y;
            }
        }
    } else {
        // ---- slow path (deg > 32, rare): fp32 math ----
        float S[6];
        #pragma unroll
        for (int h = 0; h < 6; h++) S[h] = 0.f;
        for (int j = start + lane; j < end; j += 32) {
            int s = g_csr[j];
            float4 a03 = ae4[s * 4 + 0], a45 = ae4[s * 4 + 1];
            S[0] += __expf(lrelu(a03.x + adh[0]));
            S[1] += __expf(lrelu(a03.y + adh[1]));
            S[2] += __expf(lrelu(a03.z + adh[2]));
            S[3] += __expf(lrelu(a03.w + adh[3]));
            S[4] += __expf(lrelu(a45.x + adh[4]));
            S[5] += __expf(lrelu(a45.y + adh[5]));
        }
        #pragma unroll
        for (int h = 0; h < 6; h++)
            #pragma unroll
            for (int o = 16; o > 0; o >>= 1)
                S[h] += __shfl_xor_sync(FULLM, S[h], o);
        float inv_sel = 0.f, ad_sel = 0.f;
        #pragma unroll
        for (int h = 0; h < 6; h++)
            if (hidx == h) { inv_sel = 1.f / S[h]; ad_sel = adh[h]; }

        bool act_agg = (DOUT == 32) ? actl : (actl && eo == 0);
        int dlane = (DOUT == 32) ? lane : ll;
        for (int j = start; j < end; j++) {
            int s0 = g_csr[j];
            float a = 0.f;
            uint4 v = {0,0,0,0};
            if (act_agg) {
                float e = lrelu(aef[s0 * 16 + hidx] + ad_sel);
                a = __expf(e) * inv_sel;
                v = gh[(size_t)s0 * NU4 + dlane];
            }
            float2 t;
            t = __half22float2(u2h(v.x)); f[0] += t.x * a; f[1] += t.y * a;
            t = __half22float2(u2h(v.y)); f[2] += t.x * a; f[3] += t.y * a;
            t = __half22float2(u2h(v.z)); f[4] += t.x * a; f[5] += t.y * a;
            t = __half22float2(u2h(v.w)); f[6] += t.x * a; f[7] += t.y * a;
        }
    }

    // ---- common epilogue: smem transpose, head mean + bias + SELU ----
    __syncwarp();
    if constexpr (DOUT == 32) {
        if (actl) {
            int b = lane * 8;
            #pragma unroll
            for (int k = 0; k < 8; k++) sw[b + k] = f[k];
        }
        __syncwarp();
        float o0 = sw[lane] + sw[32 + lane] + sw[64 + lane] +
                   sw[96 + lane] + sw[128 + lane] + sw[160 + lane];
        out[n * 32 + lane] = selu_f(o0 * (1.f / 6.f) + bias[lane]);
    } else {
        if (actl) {
            int b = eo * 96 + ll * 8;
            #pragma unroll
            for (int k = 0; k < 8; k++) sw[b + k] = f[k];
        }
        __syncwarp();
        if (lane < 16) {
            float o0 = 0.f;
            #pragma unroll
            for (int h = 0; h < 6; h++)
                o0 += sw[h * 16 + lane] + sw[96 + h * 16 + lane];
            out[n * 16 + lane] = selu_f(o0 * (1.f / 6.f) + bias[lane]);
        }
    }
}

// ---------------- host launcher ---------------------------------------------
extern "C" void kernel_launch(void* const* d_in, const int* in_sizes, int n_in,
                              void* d_out, int out_size) {
    (void)in_sizes; (void)n_in; (void)out_size;
    const float* x     = (const float*)d_in[0];
    const int*   ei    = (const int*)d_in[1];
    const float* lin_w = (const float*)d_in[2];
    const float* lin_b = (const float*)d_in[3];
    const float* W[4]  = { (const float*)d_in[4],  (const float*)d_in[8],
                           (const float*)d_in[12], (const float*)d_in[16] };
    const float* AS[4] = { (const float*)d_in[5],  (const float*)d_in[9],
                           (const float*)d_in[13], (const float*)d_in[17] };
    const float* AD[4] = { (const float*)d_in[6],  (const float*)d_in[10],
                           (const float*)d_in[14], (const float*)d_in[18] };
    const float* B[4]  = { (const float*)d_in[7],  (const float*)d_in[11],
                           (const float*)d_in[15], (const float*)d_in[19] };
    float* out = (float*)d_out;

    float* g_hin_ptr = nullptr;
    cudaGetSymbolAddress((void**)&g_hin_ptr, g_hin4);

    const int gat_blocks = NN / 8;

    // 0: count + lin0 + wa
    k_count_lin0<<<CNT_BLOCKS + LIN0_BLOCKS + 1, 256>>>(
        ei, x, lin_w, lin_b,
        W[0], AS[0], AD[0], W[1], AS[1], AD[1],
        W[2], AS[2], AD[2], W[3], AS[3], AD[3]);
    // 1: scan
    k_scan<<<1, 1024>>>();
    // 2: scatter + feat layer 1 (fused, independent block ranges)
    k_scatter_feat1<<<SCAT_BLOCKS + FEAT_BLOCKS, 256>>>(ei, W[0]);
    // 3: gat layer 1   <- ncu capture target
    k_gat<32><<<gat_blocks, 256>>>(B[0], g_hin_ptr);
    // 4-5: layer 2
    k_feat<32, 32, 192, 1, false><<<FEAT_BLOCKS, 256>>>(W[1]);
    k_gat<32><<<gat_blocks, 256>>>(B[1], g_hin_ptr);
    // 6-7: layer 3
    k_feat<32, 16, 96, 2, false><<<FEAT_BLOCKS, 256>>>(W[2]);
    k_gat<16><<<gat_blocks, 256>>>(B[2], g_hin_ptr);
    // 8-9: layer 4 (+cursor re-zero for next call)
    k_feat<16, 2, 16, 3, true><<<FEAT_BLOCKS + CDIV(NN, 256), 256>>>(W[3]);
    k_gat<2><<<gat_blocks, 256>>>(B[3], out);
}

// round 16
// speedup vs baseline: 1.0369x; 1.0055x over previous
#include <cuda_runtime.h>
#include <cuda_fp16.h>

#define NN 50000
#define EE 800000
#define ET (EE + NN)   // edges + self loops
#define FULLM 0xffffffffu

__host__ __device__ constexpr int CDIV(int a, int b) { return (a + b - 1) / b; }

// ---------------- scratch (static __device__ globals; no allocs) -------------
__device__ __align__(16) int g_rowptr[NN + 4];
__device__ __align__(16) int g_cursor[NN];       // zero at call start (invariant)
__device__ int    g_csr[ET];
__device__ float4 g_hin4[NN * 8];        // node features [n][din] fp32, din<=32
__device__ __align__(128) __half g_hh[NN * 192];  // transformed features, fp16
__device__ float4 g_ae4[NN * 4];         // [n][16]: 0..5 src logits, 8..13 dst logits
__device__ float  g_wa[4 * 384];         // folded attention mats: [l][d*12+hh]

__device__ __forceinline__ float selu_f(float x) {
    const float sc = 1.0507009873554805f;
    const float al = 1.6732632423543772f;
    return x > 0.f ? sc * x : sc * al * (__expf(x) - 1.f);
}
__device__ __forceinline__ float lrelu(float x) { return x > 0.f ? x : 0.2f * x; }
__device__ __forceinline__ float f4c(const float4& v, int j) {
    return j == 0 ? v.x : j == 1 ? v.y : j == 2 ? v.z : v.w;
}
__device__ __forceinline__ void fma4(float4& a, const float4& v, float s) {
    a.x += v.x * s; a.y += v.y * s; a.z += v.z * s; a.w += v.w * s;
}
__device__ __forceinline__ uint2 f4_to_h4(float4 a) {
    __half2 lo = __floats2half2_rn(a.x, a.y);
    __half2 hi = __floats2half2_rn(a.z, a.w);
    uint2 r;
    r.x = *reinterpret_cast<unsigned*>(&lo);
    r.y = *reinterpret_cast<unsigned*>(&hi);
    return r;
}
__device__ __forceinline__ __half2 u2h(unsigned u) {
    return *reinterpret_cast<__half2*>(&u);
}

// ---------------- launch 0: count + lin0 + wa precompute --------------------
#define CNT_BLOCKS  CDIV(EE, 256)
#define LIN0_BLOCKS CDIV(NN * 16, 256)
__global__ __launch_bounds__(256) void k_count_lin0(
    const int* __restrict__ ei, const float* __restrict__ x,
    const float* __restrict__ lw, const float* __restrict__ lb,
    const float* __restrict__ W1, const float* __restrict__ AS1, const float* __restrict__ AD1,
    const float* __restrict__ W2, const float* __restrict__ AS2, const float* __restrict__ AD2,
    const float* __restrict__ W3, const float* __restrict__ AS3, const float* __restrict__ AD3,
    const float* __restrict__ W4, const float* __restrict__ AS4, const float* __restrict__ AD4) {
    if (blockIdx.x < CNT_BLOCKS) {
        int i = blockIdx.x * 256 + threadIdx.x;
        if (i < EE) atomicAdd(&g_cursor[ei[EE + i]], 1);
    } else if (blockIdx.x < CNT_BLOCKS + LIN0_BLOCKS) {
        int i = (blockIdx.x - CNT_BLOCKS) * 256 + threadIdx.x;
        if (i >= NN * 16) return;
        int n = i >> 4, c = i & 15;
        const float* xr = x + n * 10;
        const float* wr = lw + c * 10;
        float acc = lb[c];
        #pragma unroll
        for (int d = 0; d < 10; d++) acc += xr[d] * wr[d];
        reinterpret_cast<float*>(g_hin4)[i] = selu_f(acc);
    } else {
        const float* Ws[4]  = {W1, W2, W3, W4};
        const float* ASs[4] = {AS1, AS2, AS3, AS4};
        const float* ADs[4] = {AD1, AD2, AD3, AD4};
        const int din[4]  = {16, 32, 32, 16};
        const int dout[4] = {32, 32, 16, 2};
        for (int e = threadIdx.x; e < 4 * 384; e += 256) {
            int l = e / 384, r = e - l * 384, d = r / 12, hh = r - d * 12;
            if (d >= din[l]) continue;
            int head = hh % 6;
            int DO = dout[l], DI = din[l];
            const float* av = (hh < 6 ? ASs[l] : ADs[l]) + head * DO;
            const float* Wl = Ws[l];
            float s = 0.f;
            for (int o = 0; o < DO; o++) s += av[o] * Wl[(head * DO + o) * DI + d];
            g_wa[e] = s;
        }
    }
}

// ---------------- launch 1: scan, 4 elems/thread (adds self-loop +1) --------
__global__ void k_scan() {
    __shared__ int s_wtot[33];
    __shared__ int s_carry;
    int tid = threadIdx.x, lane = tid & 31, wid = tid >> 5;
    if (tid == 0) s_carry = 0;
    __syncthreads();
    const int4* cur4 = reinterpret_cast<const int4*>(g_cursor);
    int4* cw4 = reinterpret_cast<int4*>(g_cursor);
    int4* rp4 = reinterpret_cast<int4*>(g_rowptr);
    constexpr int N4 = NN / 4;       // 12500
    for (int base = 0; base < N4; base += 1024) {
        int i4 = base + tid;
        int4 v = {0, 0, 0, 0};
        if (i4 < N4) {
            v = cur4[i4];
            v.x++; v.y++; v.z++; v.w++;   // self loops
        }
        int t0 = v.x, t1 = t0 + v.y, t2 = t1 + v.z, t3 = t2 + v.w;
        int x = t3;
        #pragma unroll
        for (int o = 1; o < 32; o <<= 1) {
            int t = __shfl_up_sync(FULLM, x, o);
            if (lane >= o) x += t;
        }
        if (lane == 31) s_wtot[wid] = x;
        __syncthreads();
        if (wid == 0) {
            int w = s_wtot[lane];
            int y = w;
            #pragma unroll
            for (int o = 1; o < 32; o <<= 1) {
                int t = __shfl_up_sync(FULLM, y, o);
                if (lane >= o) y += t;
            }
            s_wtot[lane] = y - w;
            if (lane == 31) s_wtot[32] = y;
        }
        __syncthreads();
        int excl = s_carry + s_wtot[wid] + (x - t3);
        if (i4 < N4) {
            int4 r;
            r.x = excl; r.y = excl + t0; r.z = excl + t1; r.w = excl + t2;
            rp4[i4] = r;
            cw4[i4] = r;
        }
        int btot = s_wtot[32];
        __syncthreads();
        if (tid == 0) s_carry += btot;
        __syncthreads();
    }
    if (tid == 0) g_rowptr[NN] = s_carry;
}

// ---------------- transform / alpha device functions ------------------------
#define TILES 8
// 2 nodes per thread; c4-major thread order (coalesced writes, broadcast x reads)
template <int DIN, int DOUT, int STRIDE>
__device__ __forceinline__ void dev_transform(float* s_buf, int blk,
                                              const float* __restrict__ W) {
    constexpr int HD = 6 * DOUT;
    constexpr int C4 = HD / 4;
    constexpr int C4S = STRIDE / 4;
    constexpr int TOT = (NN / 2) * C4S;
    for (int i = threadIdx.x; i < DIN * HD; i += 256) {
        int k = i / DIN, d = i - k * DIN;
        s_buf[d * HD + k] = W[i];
    }
    __syncthreads();
    #pragma unroll
    for (int rep = 0; rep < TILES; rep++) {
        int t = (blk * TILES + rep) * 256 + threadIdx.x;
        if (t >= TOT) return;
        int c4 = t % C4S, nb = t / C4S;
        int n0 = nb * 2;
        float4 acc0 = {0,0,0,0}, acc1 = {0,0,0,0};
        if (c4 < C4) {
            const float4* x4 = g_hin4;
            const float4* w4 = reinterpret_cast<const float4*>(s_buf);
            #pragma unroll
            for (int dc = 0; dc < DIN / 4; dc++) {
                float4 xv0 = x4[(n0 + 0) * (DIN / 4) + dc];
                float4 xv1 = x4[(n0 + 1) * (DIN / 4) + dc];
                #pragma unroll
                for (int j = 0; j < 4; j++) {
                    float4 wv = w4[(dc * 4 + j) * C4 + c4];
                    fma4(acc0, wv, f4c(xv0, j));
                    fma4(acc1, wv, f4c(xv1, j));
                }
            }
        }
        __half* hb = g_hh;
        *reinterpret_cast<uint2*>(hb + (size_t)(n0 + 0) * STRIDE + c4 * 4) = f4_to_h4(acc0);
        *reinterpret_cast<uint2*>(hb + (size_t)(n0 + 1) * STRIDE + c4 * 4) = f4_to_h4(acc1);
    }
}

template <int DIN, int LAYER>
__device__ __forceinline__ void dev_alpha(float* s_buf, int blk) {
    for (int i = threadIdx.x; i < DIN * 12; i += 256)
        s_buf[i] = g_wa[LAYER * 384 + i];
    __syncthreads();
    #pragma unroll
    for (int rep = 0; rep < TILES; rep++) {
        int t2 = (blk * TILES + rep) * 256 + threadIdx.x;
        if (t2 >= NN * 12) return;
        int n = t2 / 12, hh = t2 - n * 12;
        const float4* xr4 = g_hin4 + (size_t)n * (DIN / 4);
        float acc = 0.f;
        #pragma unroll
        for (int d4 = 0; d4 < DIN / 4; d4++) {
            float4 xv = xr4[d4];
            acc += xv.x * s_buf[(d4 * 4 + 0) * 12 + hh]
                 + xv.y * s_buf[(d4 * 4 + 1) * 12 + hh]
                 + xv.z * s_buf[(d4 * 4 + 2) * 12 + hh]
                 + xv.w * s_buf[(d4 * 4 + 3) * 12 + hh];
        }
        reinterpret_cast<float*>(g_ae4)[n * 16 + (hh < 6 ? hh : hh + 2)] = acc;
    }
}

#define NBA2 CDIV(CDIV(NN * 12, 256), TILES)
#define NBT_OF(STRIDE) CDIV(CDIV((NN / 2) * ((STRIDE) / 4), 256), TILES)

// ---------------- launch 2: scatter + feat layer 1, fused -------------------
#define NBT1 NBT_OF(192)
#define SCAT_BLOCKS CDIV(ET, 256)
__global__ __launch_bounds__(256) void k_scatter_feat1(const int* __restrict__ ei,
                                                       const float* __restrict__ W) {
    __shared__ float s_buf[16 * 192];
    if (blockIdx.x < SCAT_BLOCKS) {
        int i = blockIdx.x * 256 + threadIdx.x;
        if (i >= ET) return;
        int s, d;
        if (i < EE) { s = ei[i]; d = ei[EE + i]; }
        else        { s = d = i - EE; }
        int pos = atomicAdd(&g_cursor[d], 1);
        g_csr[pos] = s;
    } else if (blockIdx.x < SCAT_BLOCKS + NBT1) {
        dev_transform<16, 32, 192>(s_buf, blockIdx.x - SCAT_BLOCKS, W);
    } else {
        dev_alpha<16, 0>(s_buf, blockIdx.x - SCAT_BLOCKS - NBT1);
    }
}

// ---------------- per-layer feat (layers 2-4) -------------------------------
template <int DIN, int DOUT, int STRIDE, int LAYER, bool ZERO_CURSOR>
__global__ __launch_bounds__(256) void k_feat(const float* __restrict__ W) {
    __shared__ float s_buf[DIN * 6 * DOUT];
    constexpr int NBT = NBT_OF(STRIDE);
    if (blockIdx.x < NBT) {
        dev_transform<DIN, DOUT, STRIDE>(s_buf, blockIdx.x, W);
    } else if (blockIdx.x < NBT + NBA2) {
        dev_alpha<DIN, LAYER>(s_buf, blockIdx.x - NBT);
    } else if (ZERO_CURSOR) {
        int i = (blockIdx.x - NBT - NBA2) * 256 + threadIdx.x;
        if (i < NN) g_cursor[i] = 0;
    }
}

// ---------------- fused GAT (proven 52-us variant) ---------------------------
template <int DOUT>
__global__ __launch_bounds__(256) void k_gat(const float* __restrict__ bias,
                                             float* __restrict__ out) {
    __shared__ float s_red[(DOUT > 2) ? 8 * 216 : 8];
    int w = threadIdx.x >> 5, lane = threadIdx.x & 31;
    int n = blockIdx.x * 8 + w;           // grid = NN/8 exactly
    int start = g_rowptr[n], end = g_rowptr[n + 1];
    int deg = end - start;

    const float4* ae4 = g_ae4;
    const float*  aef = reinterpret_cast<const float*>(g_ae4);
    float4 d03 = ae4[n * 4 + 2];
    float4 d45 = ae4[n * 4 + 3];
    float adh[6] = {d03.x, d03.y, d03.z, d03.w, d45.x, d45.y};
    float* sw = s_red + ((DOUT > 2) ? w * 216 : 0);
    const uint4* gh = reinterpret_cast<const uint4*>(g_hh);

    // ================= DOUT == 2 (HD=12, stride 16 halves) =================
    if constexpr (DOUT == 2) {
        float acc[12];
        #pragma unroll
        for (int k = 0; k < 12; k++) acc[k] = 0.f;
        if (deg <= 32) {
            int s = 0; bool act = lane < deg;
            if (act) s = g_csr[start + lane];
            float p[6], S[6];
            if (act) {
                float4 a03 = ae4[s * 4 + 0], a45 = ae4[s * 4 + 1];
                p[0] = __expf(lrelu(a03.x + adh[0]));
                p[1] = __expf(lrelu(a03.y + adh[1]));
                p[2] = __expf(lrelu(a03.z + adh[2]));
                p[3] = __expf(lrelu(a03.w + adh[3]));
                p[4] = __expf(lrelu(a45.x + adh[4]));
                p[5] = __expf(lrelu(a45.y + adh[5]));
            } else {
                #pragma unroll
                for (int h = 0; h < 6; h++) p[h] = 0.f;
            }
            #pragma unroll
            for (int h = 0; h < 6; h++) S[h] = p[h];
            #pragma unroll
            for (int h = 0; h < 6; h++)
                #pragma unroll
                for (int o = 16; o > 0; o >>= 1)
                    S[h] += __shfl_xor_sync(FULLM, S[h], o);
            float al[6];
            #pragma unroll
            for (int h = 0; h < 6; h++) al[h] = p[h] * (1.f / S[h]);
            if (act) {
                const uint4* hp = gh + s * 2;
                uint4 u0 = hp[0], u1 = hp[1];
                float2 f;
                f = __half22float2(u2h(u0.x)); acc[0] = f.x * al[0]; acc[1] = f.y * al[0];
                f = __half22float2(u2h(u0.y)); acc[2] = f.x * al[1]; acc[3] = f.y * al[1];
                f = __half22float2(u2h(u0.z)); acc[4] = f.x * al[2]; acc[5] = f.y * al[2];
                f = __half22float2(u2h(u0.w)); acc[6] = f.x * al[3]; acc[7] = f.y * al[3];
                f = __half22float2(u2h(u1.x)); acc[8] = f.x * al[4]; acc[9] = f.y * al[4];
                f = __half22float2(u2h(u1.y)); acc[10] = f.x * al[5]; acc[11] = f.y * al[5];
            }
        } else {
            float S[6];
            #pragma unroll
            for (int h = 0; h < 6; h++) S[h] = 0.f;
            for (int j = start + lane; j < end; j += 32) {
                int s = g_csr[j];
                float4 a03 = ae4[s * 4 + 0], a45 = ae4[s * 4 + 1];
                S[0] += __expf(lrelu(a03.x + adh[0]));
                S[1] += __expf(lrelu(a03.y + adh[1]));
                S[2] += __expf(lrelu(a03.z + adh[2]));
                S[3] += __expf(lrelu(a03.w + adh[3]));
                S[4] += __expf(lrelu(a45.x + adh[4]));
                S[5] += __expf(lrelu(a45.y + adh[5]));
            }
            #pragma unroll
            for (int h = 0; h < 6; h++)
                #pragma unroll
                for (int o = 16; o > 0; o >>= 1)
                    S[h] += __shfl_xor_sync(FULLM, S[h], o);
            float inv[6];
            #pragma unroll
            for (int h = 0; h < 6; h++) inv[h] = 1.f / S[h];
            for (int j = start + lane; j < end; j += 32) {
                int s = g_csr[j];
                float4 a03 = ae4[s * 4 + 0], a45 = ae4[s * 4 + 1];
                float al[6];
                al[0] = __expf(lrelu(a03.x + adh[0])) * inv[0];
                al[1] = __expf(lrelu(a03.y + adh[1])) * inv[1];
                al[2] = __expf(lrelu(a03.z + adh[2])) * inv[2];
                al[3] = __expf(lrelu(a03.w + adh[3])) * inv[3];
                al[4] = __expf(lrelu(a45.x + adh[4])) * inv[4];
                al[5] = __expf(lrelu(a45.y + adh[5])) * inv[5];
                const uint4* hp = gh + s * 2;
                uint4 u0 = hp[0], u1 = hp[1];
                float2 f;
                f = __half22float2(u2h(u0.x)); acc[0] += f.x * al[0]; acc[1] += f.y * al[0];
                f = __half22float2(u2h(u0.y)); acc[2] += f.x * al[1]; acc[3] += f.y * al[1];
                f = __half22float2(u2h(u0.z)); acc[4] += f.x * al[2]; acc[5] += f.y * al[2];
                f = __half22float2(u2h(u0.w)); acc[6] += f.x * al[3]; acc[7] += f.y * al[3];
                f = __half22float2(u2h(u1.x)); acc[8] += f.x * al[4]; acc[9] += f.y * al[4];
                f = __half22float2(u2h(u1.y)); acc[10] += f.x * al[5]; acc[11] += f.y * al[5];
            }
        }
        float q0 = acc[0] + acc[2] + acc[4] + acc[6] + acc[8] + acc[10];
        float q1 = acc[1] + acc[3] + acc[5] + acc[7] + acc[9] + acc[11];
        #pragma unroll
        for (int o = 16; o > 0; o >>= 1) {
            q0 += __shfl_xor_sync(FULLM, q0, o);
            q1 += __shfl_xor_sync(FULLM, q1, o);
        }
        if (lane < 2) {
            float v = lane ? q1 : q0;
            out[n * 2 + lane] = selu_f(v * (1.f / 6.f) + bias[lane]);
        }
        return;
    }

    // ================= DOUT == 32 / 16 =================
    bool actl = lane < 24;
    int hidx, ll = 0, eo = 0;
    if constexpr (DOUT == 32) {
        hidx = actl ? (lane >> 2) : 0;
    } else {
        ll = actl ? (lane % 12) : 0;
        eo = actl ? (lane / 12) : 0;
        hidx = ll >> 1;
    }
    constexpr int NU4 = (DOUT == 32) ? 24 : 12;   // uint4 per node row
    float f[8];
    #pragma unroll
    for (int k = 0; k < 8; k++) f[k] = 0.f;
    unsigned* swu = reinterpret_cast<unsigned*>(sw);

    if (deg <= 32) {
        // ---- fast path: lane-per-edge softmax (no max shift) ----
        int s = 0; bool act = lane < deg;
        if (act) s = g_csr[start + lane];
        float p[6], S[6];
        if (act) {
            float4 a03 = ae4[s * 4 + 0], a45 = ae4[s * 4 + 1];
            p[0] = __expf(lrelu(a03.x + adh[0]));
            p[1] = __expf(lrelu(a03.y + adh[1]));
            p[2] = __expf(lrelu(a03.z + adh[2]));
            p[3] = __expf(lrelu(a03.w + adh[3]));
            p[4] = __expf(lrelu(a45.x + adh[4]));
            p[5] = __expf(lrelu(a45.y + adh[5]));
        } else {
            #pragma unroll
            for (int h = 0; h < 6; h++) p[h] = 0.f;
        }
        #pragma unroll
        for (int h = 0; h < 6; h++) S[h] = p[h];
        #pragma unroll
        for (int h = 0; h < 6; h++)
            #pragma unroll
            for (int o = 16; o > 0; o >>= 1)
                S[h] += __shfl_xor_sync(FULLM, S[h], o);
        // stage normalized alphas as broadcast half2, head-major stride 36
        #pragma unroll
        for (int h = 0; h < 6; h++) {
            __half2 ah = __float2half2_rn(p[h] * (1.f / S[h]));
            swu[h * 36 + lane] = *reinterpret_cast<unsigned*>(&ah);
        }
        __syncwarp();

        int degR = (deg + 3) & ~3;       // padded edges have alpha=0, s=0 (valid row)

        if constexpr (DOUT == 32) {
            for (int j = 0; j < degR; j += 4) {
                int s0 = __shfl_sync(FULLM, s, j);
                int s1 = __shfl_sync(FULLM, s, j + 1);
                int s2 = __shfl_sync(FULLM, s, j + 2);
                int s3 = __shfl_sync(FULLM, s, j + 3);
                uint4 au = *reinterpret_cast<const uint4*>(&swu[hidx * 36 + j]);
                __half2 a0 = u2h(au.x), a1 = u2h(au.y), a2 = u2h(au.z), a3 = u2h(au.w);
                uint4 v0 = {0,0,0,0}, v1 = {0,0,0,0}, v2 = {0,0,0,0}, v3 = {0,0,0,0};
                if (actl) {
                    v0 = gh[(size_t)s0 * NU4 + lane];
                    v1 = gh[(size_t)s1 * NU4 + lane];
                    v2 = gh[(size_t)s2 * NU4 + lane];
                    v3 = gh[(size_t)s3 * NU4 + lane];
                }
                __half2 g0 = __hmul2(u2h(v0.x), a0);
                __half2 g1 = __hmul2(u2h(v0.y), a0);
                __half2 g2 = __hmul2(u2h(v0.z), a0);
                __half2 g3 = __hmul2(u2h(v0.w), a0);
                g0 = __hfma2(u2h(v1.x), a1, g0);
                g1 = __hfma2(u2h(v1.y), a1, g1);
                g2 = __hfma2(u2h(v1.z), a1, g2);
                g3 = __hfma2(u2h(v1.w), a1, g3);
                g0 = __hfma2(u2h(v2.x), a2, g0);
                g1 = __hfma2(u2h(v2.y), a2, g1);
                g2 = __hfma2(u2h(v2.z), a2, g2);
                g3 = __hfma2(u2h(v2.w), a2, g3);
                g0 = __hfma2(u2h(v3.x), a3, g0);
                g1 = __hfma2(u2h(v3.y), a3, g1);
                g2 = __hfma2(u2h(v3.z), a3, g2);
                g3 = __hfma2(u2h(v3.w), a3, g3);
                float2 t;
                t = __half22float2(g0); f[0] += t.x; f[1] += t.y;
                t = __half22float2(g1); f[2] += t.x; f[3] += t.y;
                t = __half22float2(g2); f[4] += t.x; f[5] += t.y;
                t = __half22float2(g3); f[6] += t.x; f[7] += t.y;
            }
        } else { // DOUT == 16: 4 edges per iter (2 per eo group)
            for (int j = 0; j < degR; j += 4) {
                int js0 = j + eo, js1 = j + 2 + eo;
                int t0 = __shfl_sync(FULLM, s, js0);
                int t1 = __shfl_sync(FULLM, s, js1);
                __half2 a0 = u2h(actl ? swu[hidx * 36 + js0] : 0u);
                __half2 a1 = u2h(actl ? swu[hidx * 36 + js1] : 0u);
                uint4 v0 = {0,0,0,0}, v1 = {0,0,0,0};
                if (actl) {
                    v0 = gh[(size_t)t0 * NU4 + ll];
                    v1 = gh[(size_t)t1 * NU4 + ll];
                }
                __half2 g0 = __hmul2(u2h(v0.x), a0);
                __half2 g1 = __hmul2(u2h(v0.y), a0);
                __half2 g2 = __hmul2(u2h(v0.z), a0);
                __half2 g3 = __hmul2(u2h(v0.w), a0);
                g0 = __hfma2(u2h(v1.x), a1, g0);
                g1 = __hfma2(u2h(v1.y), a1, g1);
                g2 = __hfma2(u2h(v1.z), a1, g2);
                g3 = __hfma2(u2h(v1.w), a1, g3);
                float2 t;
                t = __half22float2(g0); f[0] += t.x; f[1] += t.y;
                t = __half22float2(g1); f[2] += t.x; f[3] += t.y;
                t = __half22float2(g2); f[4] += t.x; f[5] += t.y;
                t = __half22float2(g3); f[6] += t.x; f[7] += t.y;
            }
        }
    } else {
        // ---- slow path (deg > 32, rare): fp32 math ----
        float S[6];
        #pragma unroll
        for (int h = 0; h < 6; h++) S[h] = 0.f;
        for (int j = start + lane; j < end; j += 32) {
            int s = g_csr[j];
            float4 a03 = ae4[s * 4 + 0], a45 = ae4[s * 4 + 1];
            S[0] += __expf(lrelu(a03.x + adh[0]));
            S[1] += __expf(lrelu(a03.y + adh[1]));
            S[2] += __expf(lrelu(a03.z + adh[2]));
            S[3] += __expf(lrelu(a03.w + adh[3]));
            S[4] += __expf(lrelu(a45.x + adh[4]));
            S[5] += __expf(lrelu(a45.y + adh[5]));
        }
        #pragma unroll
        for (int h = 0; h < 6; h++)
            #pragma unroll
            for (int o = 16; o > 0; o >>= 1)
                S[h] += __shfl_xor_sync(FULLM, S[h], o);
        float inv_sel = 0.f, ad_sel = 0.f;
        #pragma unroll
        for (int h = 0; h < 6; h++)
            if (hidx == h) { inv_sel = 1.f / S[h]; ad_sel = adh[h]; }

        bool act_agg = (DOUT == 32) ? actl : (actl && eo == 0);
        int dlane = (DOUT == 32) ? lane : ll;
        for (int j = start; j < end; j++) {
            int s0 = g_csr[j];
            float a = 0.f;
            uint4 v = {0,0,0,0};
            if (act_agg) {
                float e = lrelu(aef[s0 * 16 + hidx] + ad_sel);
                a = __expf(e) * inv_sel;
                v = gh[(size_t)s0 * NU4 + dlane];
            }
            float2 t;
            t = __half22float2(u2h(v.x)); f[0] += t.x * a; f[1] += t.y * a;
            t = __half22float2(u2h(v.y)); f[2] += t.x * a; f[3] += t.y * a;
            t = __half22float2(u2h(v.z)); f[4] += t.x * a; f[5] += t.y * a;
            t = __half22float2(u2h(v.w)); f[6] += t.x * a; f[7] += t.y * a;
        }
    }

    // ---- common epilogue: smem transpose, head mean + bias + SELU ----
    __syncwarp();
    if constexpr (DOUT == 32) {
        if (actl) {
            int b = lane * 8;
            #pragma unroll
            for (int k = 0; k < 8; k++) sw[b + k] = f[k];
        }
        __syncwarp();
        float o0 = sw[lane] + sw[32 + lane] + sw[64 + lane] +
                   sw[96 + lane] + sw[128 + lane] + sw[160 + lane];
        out[n * 32 + lane] = selu_f(o0 * (1.f / 6.f) + bias[lane]);
    } else {
        if (actl) {
            int b = eo * 96 + ll * 8;
            #pragma unroll
            for (int k = 0; k < 8; k++) sw[b + k] = f[k];
        }
        __syncwarp();
        if (lane < 16) {
            float o0 = 0.f;
            #pragma unroll
            for (int h = 0; h < 6; h++)
                o0 += sw[h * 16 + lane] + sw[96 + h * 16 + lane];
            out[n * 16 + lane] = selu_f(o0 * (1.f / 6.f) + bias[lane]);
        }
    }
}

// ---------------- host launcher ---------------------------------------------
extern "C" void kernel_launch(void* const* d_in, const int* in_sizes, int n_in,
                              void* d_out, int out_size) {
    (void)in_sizes; (void)n_in; (void)out_size;
    const float* x     = (const float*)d_in[0];
    const int*   ei    = (const int*)d_in[1];
    const float* lin_w = (const float*)d_in[2];
    const float* lin_b = (const float*)d_in[3];
    const float* W[4]  = { (const float*)d_in[4],  (const float*)d_in[8],
                           (const float*)d_in[12], (const float*)d_in[16] };
    const float* AS[4] = { (const float*)d_in[5],  (const float*)d_in[9],
                           (const float*)d_in[13], (const float*)d_in[17] };
    const float* AD[4] = { (const float*)d_in[6],  (const float*)d_in[10],
                           (const float*)d_in[14], (const float*)d_in[18] };
    const float* B[4]  = { (const float*)d_in[7],  (const float*)d_in[11],
                           (const float*)d_in[15], (const float*)d_in[19] };
    float* out = (float*)d_out;

    float* g_hin_ptr = nullptr;
    cudaGetSymbolAddress((void**)&g_hin_ptr, g_hin4);

    const int gat_blocks = NN / 8;

    // 0: count + lin0 + wa
    k_count_lin0<<<CNT_BLOCKS + LIN0_BLOCKS + 1, 256>>>(
        ei, x, lin_w, lin_b,
        W[0], AS[0], AD[0], W[1], AS[1], AD[1],
        W[2], AS[2], AD[2], W[3], AS[3], AD[3]);
    // 1: scan
    k_scan<<<1, 1024>>>();
    // 2: scatter + feat layer 1 (fused, independent block ranges)
    k_scatter_feat1<<<SCAT_BLOCKS + NBT1 + NBA2, 256>>>(ei, W[0]);
    // 3: gat layer 1   <- ncu capture target
    k_gat<32><<<gat_blocks, 256>>>(B[0], g_hin_ptr);
    // 4-5: layer 2
    k_feat<32, 32, 192, 1, false><<<NBT_OF(192) + NBA2, 256>>>(W[1]);
    k_gat<32><<<gat_blocks, 256>>>(B[1], g_hin_ptr);
    // 6-7: layer 3
    k_feat<32, 16, 96, 2, false><<<NBT_OF(96) + NBA2, 256>>>(W[2]);
    k_gat<16><<<gat_blocks, 256>>>(B[2], g_hin_ptr);
    // 8-9: layer 4 (+cursor re-zero for next call)
    k_feat<16, 2, 16, 3, true><<<NBT_OF(16) + NBA2 + CDIV(NN, 256), 256>>>(W[3]);
    k_gat<2><<<gat_blocks, 256>>>(B[3], out);
}

// round 17
// speedup vs baseline: 1.0879x; 1.0492x over previous
#include <cuda_runtime.h>
#include <cuda_fp16.h>

#define NN 50000
#define EE 800000
#define ET (EE + NN)   // edges + self loops
#define FULLM 0xffffffffu

__host__ __device__ constexpr int CDIV(int a, int b) { return (a + b - 1) / b; }

// ---------------- scratch (static __device__ globals; no allocs) -------------
__device__ __align__(16) int g_rowptr[NN + 4];
__device__ __align__(16) int g_cursor[NN];       // zero at call start (invariant)
__device__ int    g_csr[ET];
__device__ float4 g_hin4[NN * 8];        // node features [n][din] fp32, din<=32
__device__ __align__(128) __half g_hh[NN * 192];  // transformed features, fp16
__device__ float4 g_ae4[NN * 4];         // [n][16]: 0..5 src logits, 8..13 dst logits
__device__ float  g_wa[4 * 384];         // folded attention mats: [l][d*12+hh]

__device__ __forceinline__ float selu_f(float x) {
    const float sc = 1.0507009873554805f;
    const float al = 1.6732632423543772f;
    return x > 0.f ? sc * x : sc * al * (__expf(x) - 1.f);
}
__device__ __forceinline__ float lrelu(float x) { return x > 0.f ? x : 0.2f * x; }
__device__ __forceinline__ float f4c(const float4& v, int j) {
    return j == 0 ? v.x : j == 1 ? v.y : j == 2 ? v.z : v.w;
}
__device__ __forceinline__ void fma4(float4& a, const float4& v, float s) {
    a.x += v.x * s; a.y += v.y * s; a.z += v.z * s; a.w += v.w * s;
}
__device__ __forceinline__ uint2 f4_to_h4(float4 a) {
    __half2 lo = __floats2half2_rn(a.x, a.y);
    __half2 hi = __floats2half2_rn(a.z, a.w);
    uint2 r;
    r.x = *reinterpret_cast<unsigned*>(&lo);
    r.y = *reinterpret_cast<unsigned*>(&hi);
    return r;
}
__device__ __forceinline__ __half2 u2h(unsigned u) {
    return *reinterpret_cast<__half2*>(&u);
}

// ---------------- launch 0: count + lin0 + wa precompute --------------------
#define CNT_BLOCKS  CDIV(EE, 256)
#define LIN0_BLOCKS CDIV(NN * 16, 256)
__global__ __launch_bounds__(256) void k_count_lin0(
    const int* __restrict__ ei, const float* __restrict__ x,
    const float* __restrict__ lw, const float* __restrict__ lb,
    const float* __restrict__ W1, const float* __restrict__ AS1, const float* __restrict__ AD1,
    const float* __restrict__ W2, const float* __restrict__ AS2, const float* __restrict__ AD2,
    const float* __restrict__ W3, const float* __restrict__ AS3, const float* __restrict__ AD3,
    const float* __restrict__ W4, const float* __restrict__ AS4, const float* __restrict__ AD4) {
    if (blockIdx.x < CNT_BLOCKS) {
        int i = blockIdx.x * 256 + threadIdx.x;
        if (i < EE) atomicAdd(&g_cursor[ei[EE + i]], 1);
    } else if (blockIdx.x < CNT_BLOCKS + LIN0_BLOCKS) {
        int i = (blockIdx.x - CNT_BLOCKS) * 256 + threadIdx.x;
        if (i >= NN * 16) return;
        int n = i >> 4, c = i & 15;
        const float* xr = x + n * 10;
        const float* wr = lw + c * 10;
        float acc = lb[c];
        #pragma unroll
        for (int d = 0; d < 10; d++) acc += xr[d] * wr[d];
        reinterpret_cast<float*>(g_hin4)[i] = selu_f(acc);
    } else {
        const float* Ws[4]  = {W1, W2, W3, W4};
        const float* ASs[4] = {AS1, AS2, AS3, AS4};
        const float* ADs[4] = {AD1, AD2, AD3, AD4};
        const int din[4]  = {16, 32, 32, 16};
        const int dout[4] = {32, 32, 16, 2};
        for (int e = threadIdx.x; e < 4 * 384; e += 256) {
            int l = e / 384, r = e - l * 384, d = r / 12, hh = r - d * 12;
            if (d >= din[l]) continue;
            int head = hh % 6;
            int DO = dout[l], DI = din[l];
            const float* av = (hh < 6 ? ASs[l] : ADs[l]) + head * DO;
            const float* Wl = Ws[l];
            float s = 0.f;
            for (int o = 0; o < DO; o++) s += av[o] * Wl[(head * DO + o) * DI + d];
            g_wa[e] = s;
        }
    }
}

// ---------------- launch 1: scan, 4 elems/thread (adds self-loop +1) --------
__global__ void k_scan() {
    __shared__ int s_wtot[33];
    __shared__ int s_carry;
    int tid = threadIdx.x, lane = tid & 31, wid = tid >> 5;
    if (tid == 0) s_carry = 0;
    __syncthreads();
    const int4* cur4 = reinterpret_cast<const int4*>(g_cursor);
    int4* cw4 = reinterpret_cast<int4*>(g_cursor);
    int4* rp4 = reinterpret_cast<int4*>(g_rowptr);
    constexpr int N4 = NN / 4;       // 12500
    for (int base = 0; base < N4; base += 1024) {
        int i4 = base + tid;
        int4 v = {0, 0, 0, 0};
        if (i4 < N4) {
            v = cur4[i4];
            v.x++; v.y++; v.z++; v.w++;   // self loops
        }
        int t0 = v.x, t1 = t0 + v.y, t2 = t1 + v.z, t3 = t2 + v.w;
        int x = t3;
        #pragma unroll
        for (int o = 1; o < 32; o <<= 1) {
            int t = __shfl_up_sync(FULLM, x, o);
            if (lane >= o) x += t;
        }
        if (lane == 31) s_wtot[wid] = x;
        __syncthreads();
        if (wid == 0) {
            int w = s_wtot[lane];
            int y = w;
            #pragma unroll
            for (int o = 1; o < 32; o <<= 1) {
                int t = __shfl_up_sync(FULLM, y, o);
                if (lane >= o) y += t;
            }
            s_wtot[lane] = y - w;
            if (lane == 31) s_wtot[32] = y;
        }
        __syncthreads();
        int excl = s_carry + s_wtot[wid] + (x - t3);
        if (i4 < N4) {
            int4 r;
            r.x = excl; r.y = excl + t0; r.z = excl + t1; r.w = excl + t2;
            rp4[i4] = r;
            cw4[i4] = r;
        }
        int btot = s_wtot[32];
        __syncthreads();
        if (tid == 0) s_carry += btot;
        __syncthreads();
    }
    if (tid == 0) g_rowptr[NN] = s_carry;
}

// ---------------- transform / alpha device functions (R9 proven config) ------
#define TILES 8
template <int DIN, int DOUT, int STRIDE>
__device__ __forceinline__ void dev_transform(float* s_buf, int blk,
                                              const float* __restrict__ W) {
    constexpr int HD = 6 * DOUT;
    constexpr int C4 = HD / 4;
    constexpr int C4S = STRIDE / 4;
    constexpr int TOT = (NN / 4) * C4S;
    for (int i = threadIdx.x; i < DIN * HD; i += 256) {
        int k = i / DIN, d = i - k * DIN;
        s_buf[d * HD + k] = W[i];
    }
    __syncthreads();
    #pragma unroll
    for (int rep = 0; rep < TILES; rep++) {
        int t = (blk * TILES + rep) * 256 + threadIdx.x;
        if (t >= TOT) return;
        int c4 = t % C4S, nb = t / C4S;
        int n0 = nb * 4;
        float4 acc0 = {0,0,0,0}, acc1 = {0,0,0,0}, acc2 = {0,0,0,0}, acc3 = {0,0,0,0};
        if (c4 < C4) {
            const float4* x4 = g_hin4;
            const float4* w4 = reinterpret_cast<const float4*>(s_buf);
            #pragma unroll
            for (int dc = 0; dc < DIN / 4; dc++) {
                float4 xv0 = x4[(n0 + 0) * (DIN / 4) + dc];
                float4 xv1 = x4[(n0 + 1) * (DIN / 4) + dc];
                float4 xv2 = x4[(n0 + 2) * (DIN / 4) + dc];
                float4 xv3 = x4[(n0 + 3) * (DIN / 4) + dc];
                #pragma unroll
                for (int j = 0; j < 4; j++) {
                    float4 wv = w4[(dc * 4 + j) * C4 + c4];
                    fma4(acc0, wv, f4c(xv0, j));
                    fma4(acc1, wv, f4c(xv1, j));
                    fma4(acc2, wv, f4c(xv2, j));
                    fma4(acc3, wv, f4c(xv3, j));
                }
            }
        }
        __half* hb = g_hh;
        *reinterpret_cast<uint2*>(hb + (size_t)(n0 + 0) * STRIDE + c4 * 4) = f4_to_h4(acc0);
        *reinterpret_cast<uint2*>(hb + (size_t)(n0 + 1) * STRIDE + c4 * 4) = f4_to_h4(acc1);
        *reinterpret_cast<uint2*>(hb + (size_t)(n0 + 2) * STRIDE + c4 * 4) = f4_to_h4(acc2);
        *reinterpret_cast<uint2*>(hb + (size_t)(n0 + 3) * STRIDE + c4 * 4) = f4_to_h4(acc3);
    }
}

template <int DIN, int LAYER>
__device__ __forceinline__ void dev_alpha(float* s_buf, int blk) {
    for (int i = threadIdx.x; i < DIN * 12; i += 256)
        s_buf[i] = g_wa[LAYER * 384 + i];
    __syncthreads();
    #pragma unroll
    for (int rep = 0; rep < TILES; rep++) {
        int t2 = (blk * TILES + rep) * 256 + threadIdx.x;
        if (t2 >= NN * 12) return;
        int n = t2 / 12, hh = t2 - n * 12;
        const float4* xr4 = g_hin4 + (size_t)n * (DIN / 4);
        float acc = 0.f;
        #pragma unroll
        for (int d4 = 0; d4 < DIN / 4; d4++) {
            float4 xv = xr4[d4];
            acc += xv.x * s_buf[(d4 * 4 + 0) * 12 + hh]
                 + xv.y * s_buf[(d4 * 4 + 1) * 12 + hh]
                 + xv.z * s_buf[(d4 * 4 + 2) * 12 + hh]
                 + xv.w * s_buf[(d4 * 4 + 3) * 12 + hh];
        }
        reinterpret_cast<float*>(g_ae4)[n * 16 + (hh < 6 ? hh : hh + 2)] = acc;
    }
}

#define NBA2 CDIV(CDIV(NN * 12, 256), TILES)

// ---------------- launch 2: scatter + feat layer 1, fused -------------------
#define NBT1 CDIV(CDIV((NN / 4) * 48, 256), TILES)
#define SCAT_BLOCKS CDIV(ET, 256)
__global__ __launch_bounds__(256) void k_scatter_feat1(const int* __restrict__ ei,
                                                       const float* __restrict__ W) {
    __shared__ float s_buf[16 * 192];
    if (blockIdx.x < SCAT_BLOCKS) {
        int i = blockIdx.x * 256 + threadIdx.x;
        if (i >= ET) return;
        int s, d;
        if (i < EE) { s = ei[i]; d = ei[EE + i]; }
        else        { s = d = i - EE; }
        int pos = atomicAdd(&g_cursor[d], 1);
        g_csr[pos] = s;
    } else if (blockIdx.x < SCAT_BLOCKS + NBT1) {
        dev_transform<16, 32, 192>(s_buf, blockIdx.x - SCAT_BLOCKS, W);
    } else {
        dev_alpha<16, 0>(s_buf, blockIdx.x - SCAT_BLOCKS - NBT1);
    }
}

// ---------------- per-layer feat (layers 2-4) -------------------------------
template <int DIN, int DOUT, int STRIDE, int LAYER, bool ZERO_CURSOR>
__global__ __launch_bounds__(256) void k_feat(const float* __restrict__ W) {
    __shared__ float s_buf[DIN * 6 * DOUT];
    constexpr int NBT = CDIV(CDIV((NN / 4) * (STRIDE / 4), 256), TILES);
    if (blockIdx.x < NBT) {
        dev_transform<DIN, DOUT, STRIDE>(s_buf, blockIdx.x, W);
    } else if (blockIdx.x < NBT + NBA2) {
        dev_alpha<DIN, LAYER>(s_buf, blockIdx.x - NBT);
    } else if (ZERO_CURSOR) {
        int i = (blockIdx.x - NBT - NBA2) * 256 + threadIdx.x;
        if (i < NN) g_cursor[i] = 0;
    }
}

// ---------------- fused GAT (52-us variant + byte-offset shfl) ---------------
template <int DOUT>
__global__ __launch_bounds__(256) void k_gat(const float* __restrict__ bias,
                                             float* __restrict__ out) {
    __shared__ float s_red[(DOUT > 2) ? 8 * 216 : 8];
    int w = threadIdx.x >> 5, lane = threadIdx.x & 31;
    int n = blockIdx.x * 8 + w;           // grid = NN/8 exactly
    int start = g_rowptr[n], end = g_rowptr[n + 1];
    int deg = end - start;

    const float4* ae4 = g_ae4;
    const float*  aef = reinterpret_cast<const float*>(g_ae4);
    float4 d03 = ae4[n * 4 + 2];
    float4 d45 = ae4[n * 4 + 3];
    float adh[6] = {d03.x, d03.y, d03.z, d03.w, d45.x, d45.y};
    float* sw = s_red + ((DOUT > 2) ? w * 216 : 0);
    const uint4* gh = reinterpret_cast<const uint4*>(g_hh);

    // ================= DOUT == 2 (HD=12, stride 16 halves) =================
    if constexpr (DOUT == 2) {
        float acc[12];
        #pragma unroll
        for (int k = 0; k < 12; k++) acc[k] = 0.f;
        if (deg <= 32) {
            int s = 0; bool act = lane < deg;
            if (act) s = g_csr[start + lane];
            float p[6], S[6];
            if (act) {
                float4 a03 = ae4[s * 4 + 0], a45 = ae4[s * 4 + 1];
                p[0] = __expf(lrelu(a03.x + adh[0]));
                p[1] = __expf(lrelu(a03.y + adh[1]));
                p[2] = __expf(lrelu(a03.z + adh[2]));
                p[3] = __expf(lrelu(a03.w + adh[3]));
                p[4] = __expf(lrelu(a45.x + adh[4]));
                p[5] = __expf(lrelu(a45.y + adh[5]));
            } else {
                #pragma unroll
                for (int h = 0; h < 6; h++) p[h] = 0.f;
            }
            #pragma unroll
            for (int h = 0; h < 6; h++) S[h] = p[h];
            #pragma unroll
            for (int h = 0; h < 6; h++)
                #pragma unroll
                for (int o = 16; o > 0; o >>= 1)
                    S[h] += __shfl_xor_sync(FULLM, S[h], o);
            float al[6];
            #pragma unroll
            for (int h = 0; h < 6; h++) al[h] = p[h] * (1.f / S[h]);
            if (act) {
                const uint4* hp = gh + s * 2;
                uint4 u0 = hp[0], u1 = hp[1];
                float2 f;
                f = __half22float2(u2h(u0.x)); acc[0] = f.x * al[0]; acc[1] = f.y * al[0];
                f = __half22float2(u2h(u0.y)); acc[2] = f.x * al[1]; acc[3] = f.y * al[1];
                f = __half22float2(u2h(u0.z)); acc[4] = f.x * al[2]; acc[5] = f.y * al[2];
                f = __half22float2(u2h(u0.w)); acc[6] = f.x * al[3]; acc[7] = f.y * al[3];
                f = __half22float2(u2h(u1.x)); acc[8] = f.x * al[4]; acc[9] = f.y * al[4];
                f = __half22float2(u2h(u1.y)); acc[10] = f.x * al[5]; acc[11] = f.y * al[5];
            }
        } else {
            float S[6];
            #pragma unroll
            for (int h = 0; h < 6; h++) S[h] = 0.f;
            for (int j = start + lane; j < end; j += 32) {
                int s = g_csr[j];
                float4 a03 = ae4[s * 4 + 0], a45 = ae4[s * 4 + 1];
                S[0] += __expf(lrelu(a03.x + adh[0]));
                S[1] += __expf(lrelu(a03.y + adh[1]));
                S[2] += __expf(lrelu(a03.z + adh[2]));
                S[3] += __expf(lrelu(a03.w + adh[3]));
                S[4] += __expf(lrelu(a45.x + adh[4]));
                S[5] += __expf(lrelu(a45.y + adh[5]));
            }
            #pragma unroll
            for (int h = 0; h < 6; h++)
                #pragma unroll
                for (int o = 16; o > 0; o >>= 1)
                    S[h] += __shfl_xor_sync(FULLM, S[h], o);
            float inv[6];
            #pragma unroll
            for (int h = 0; h < 6; h++) inv[h] = 1.f / S[h];
            for (int j = start + lane; j < end; j += 32) {
                int s = g_csr[j];
                float4 a03 = ae4[s * 4 + 0], a45 = ae4[s * 4 + 1];
                float al[6];
                al[0] = __expf(lrelu(a03.x + adh[0])) * inv[0];
                al[1] = __expf(lrelu(a03.y + adh[1])) * inv[1];
                al[2] = __expf(lrelu(a03.z + adh[2])) * inv[2];
                al[3] = __expf(lrelu(a03.w + adh[3])) * inv[3];
                al[4] = __expf(lrelu(a45.x + adh[4])) * inv[4];
                al[5] = __expf(lrelu(a45.y + adh[5])) * inv[5];
                const uint4* hp = gh + s * 2;
                uint4 u0 = hp[0], u1 = hp[1];
                float2 f;
                f = __half22float2(u2h(u0.x)); acc[0] += f.x * al[0]; acc[1] += f.y * al[0];
                f = __half22float2(u2h(u0.y)); acc[2] += f.x * al[1]; acc[3] += f.y * al[1];
                f = __half22float2(u2h(u0.z)); acc[4] += f.x * al[2]; acc[5] += f.y * al[2];
                f = __half22float2(u2h(u0.w)); acc[6] += f.x * al[3]; acc[7] += f.y * al[3];
                f = __half22float2(u2h(u1.x)); acc[8] += f.x * al[4]; acc[9] += f.y * al[4];
                f = __half22float2(u2h(u1.y)); acc[10] += f.x * al[5]; acc[11] += f.y * al[5];
            }
        }
        float q0 = acc[0] + acc[2] + acc[4] + acc[6] + acc[8] + acc[10];
        float q1 = acc[1] + acc[3] + acc[5] + acc[7] + acc[9] + acc[11];
        #pragma unroll
        for (int o = 16; o > 0; o >>= 1) {
            q0 += __shfl_xor_sync(FULLM, q0, o);
            q1 += __shfl_xor_sync(FULLM, q1, o);
        }
        if (lane < 2) {
            float v = lane ? q1 : q0;
            out[n * 2 + lane] = selu_f(v * (1.f / 6.f) + bias[lane]);
        }
        return;
    }

    // ================= DOUT == 32 / 16 =================
    bool actl = lane < 24;
    int hidx, ll = 0, eo = 0;
    if constexpr (DOUT == 32) {
        hidx = actl ? (lane >> 2) : 0;
    } else {
        ll = actl ? (lane % 12) : 0;
        eo = actl ? (lane / 12) : 0;
        hidx = ll >> 1;
    }
    constexpr int NU4 = (DOUT == 32) ? 24 : 12;   // uint4 per node row
    constexpr int ROWB = NU4 * 16;                // row bytes
    float f[8];
    #pragma unroll
    for (int k = 0; k < 8; k++) f[k] = 0.f;
    unsigned* swu = reinterpret_cast<unsigned*>(sw);

    if (deg <= 32) {
        // ---- fast path: lane-per-edge softmax (no max shift) ----
        int s = 0; bool act = lane < deg;
        if (act) s = g_csr[start + lane];
        float p[6], S[6];
        if (act) {
            float4 a03 = ae4[s * 4 + 0], a45 = ae4[s * 4 + 1];
            p[0] = __expf(lrelu(a03.x + adh[0]));
            p[1] = __expf(lrelu(a03.y + adh[1]));
            p[2] = __expf(lrelu(a03.z + adh[2]));
            p[3] = __expf(lrelu(a03.w + adh[3]));
            p[4] = __expf(lrelu(a45.x + adh[4]));
            p[5] = __expf(lrelu(a45.y + adh[5]));
        } else {
            #pragma unroll
            for (int h = 0; h < 6; h++) p[h] = 0.f;
        }
        #pragma unroll
        for (int h = 0; h < 6; h++) S[h] = p[h];
        #pragma unroll
        for (int h = 0; h < 6; h++)
            #pragma unroll
            for (int o = 16; o > 0; o >>= 1)
                S[h] += __shfl_xor_sync(FULLM, S[h], o);
        // stage normalized alphas as broadcast half2, head-major stride 36
        #pragma unroll
        for (int h = 0; h < 6; h++) {
            __half2 ah = __float2half2_rn(p[h] * (1.f / S[h]));
            swu[h * 36 + lane] = *reinterpret_cast<unsigned*>(&ah);
        }
        __syncwarp();

        int boff = s * ROWB;             // per-lane byte offset (padding lanes: 0)
        int degR = (deg + 3) & ~3;       // padded edges have alpha=0, s=0 (valid row)

        if constexpr (DOUT == 32) {
            const char* baseb = reinterpret_cast<const char*>(gh) + lane * 16;
            for (int j = 0; j < degR; j += 4) {
                int o0 = __shfl_sync(FULLM, boff, j);
                int o1 = __shfl_sync(FULLM, boff, j + 1);
                int o2 = __shfl_sync(FULLM, boff, j + 2);
                int o3 = __shfl_sync(FULLM, boff, j + 3);
                uint4 au = *reinterpret_cast<const uint4*>(&swu[hidx * 36 + j]);
                __half2 a0 = u2h(au.x), a1 = u2h(au.y), a2 = u2h(au.z), a3 = u2h(au.w);
                uint4 v0 = {0,0,0,0}, v1 = {0,0,0,0}, v2 = {0,0,0,0}, v3 = {0,0,0,0};
                if (actl) {
                    v0 = *reinterpret_cast<const uint4*>(baseb + o0);
                    v1 = *reinterpret_cast<const uint4*>(baseb + o1);
                    v2 = *reinterpret_cast<const uint4*>(baseb + o2);
                    v3 = *reinterpret_cast<const uint4*>(baseb + o3);
                }
                __half2 g0 = __hmul2(u2h(v0.x), a0);
                __half2 g1 = __hmul2(u2h(v0.y), a0);
                __half2 g2 = __hmul2(u2h(v0.z), a0);
                __half2 g3 = __hmul2(u2h(v0.w), a0);
                g0 = __hfma2(u2h(v1.x), a1, g0);
                g1 = __hfma2(u2h(v1.y), a1, g1);
                g2 = __hfma2(u2h(v1.z), a1, g2);
                g3 = __hfma2(u2h(v1.w), a1, g3);
                g0 = __hfma2(u2h(v2.x), a2, g0);
                g1 = __hfma2(u2h(v2.y), a2, g1);
                g2 = __hfma2(u2h(v2.z), a2, g2);
                g3 = __hfma2(u2h(v2.w), a2, g3);
                g0 = __hfma2(u2h(v3.x), a3, g0);
                g1 = __hfma2(u2h(v3.y), a3, g1);
                g2 = __hfma2(u2h(v3.z), a3, g2);
                g3 = __hfma2(u2h(v3.w), a3, g3);
                float2 t;
                t = __half22float2(g0); f[0] += t.x; f[1] += t.y;
                t = __half22float2(g1); f[2] += t.x; f[3] += t.y;
                t = __half22float2(g2); f[4] += t.x; f[5] += t.y;
                t = __half22float2(g3); f[6] += t.x; f[7] += t.y;
            }
        } else { // DOUT == 16: 4 edges per iter (2 per eo group)
            const char* baseb = reinterpret_cast<const char*>(gh) + ll * 16;
            for (int j = 0; j < degR; j += 4) {
                int js0 = j + eo, js1 = j + 2 + eo;
                int o0 = __shfl_sync(FULLM, boff, js0);
                int o1 = __shfl_sync(FULLM, boff, js1);
                __half2 a0 = u2h(actl ? swu[hidx * 36 + js0] : 0u);
                __half2 a1 = u2h(actl ? swu[hidx * 36 + js1] : 0u);
                uint4 v0 = {0,0,0,0}, v1 = {0,0,0,0};
                if (actl) {
                    v0 = *reinterpret_cast<const uint4*>(baseb + o0);
                    v1 = *reinterpret_cast<const uint4*>(baseb + o1);
                }
                __half2 g0 = __hmul2(u2h(v0.x), a0);
                __half2 g1 = __hmul2(u2h(v0.y), a0);
                __half2 g2 = __hmul2(u2h(v0.z), a0);
                __half2 g3 = __hmul2(u2h(v0.w), a0);
                g0 = __hfma2(u2h(v1.x), a1, g0);
                g1 = __hfma2(u2h(v1.y), a1, g1);
                g2 = __hfma2(u2h(v1.z), a1, g2);
                g3 = __hfma2(u2h(v1.w), a1, g3);
                float2 t;
                t = __half22float2(g0); f[0] += t.x; f[1] += t.y;
                t = __half22float2(g1); f[2] += t.x; f[3] += t.y;
                t = __half22float2(g2); f[4] += t.x; f[5] += t.y;
                t = __half22float2(g3); f[6] += t.x; f[7] += t.y;
            }
        }
    } else {
        // ---- slow path (deg > 32, rare): fp32 math ----
        float S[6];
        #pragma unroll
        for (int h = 0; h < 6; h++) S[h] = 0.f;
        for (int j = start + lane; j < end; j += 32) {
            int s = g_csr[j];
            float4 a03 = ae4[s * 4 + 0], a45 = ae4[s * 4 + 1];
            S[0] += __expf(lrelu(a03.x + adh[0]));
            S[1] += __expf(lrelu(a03.y + adh[1]));
            S[2] += __expf(lrelu(a03.z + adh[2]));
            S[3] += __expf(lrelu(a03.w + adh[3]));
            S[4] += __expf(lrelu(a45.x + adh[4]));
            S[5] += __expf(lrelu(a45.y + adh[5]));
        }
        #pragma unroll
        for (int h = 0; h < 6; h++)
            #pragma unroll
            for (int o = 16; o > 0; o >>= 1)
                S[h] += __shfl_xor_sync(FULLM, S[h], o);
        float inv_sel = 0.f, ad_sel = 0.f;
        #pragma unroll
        for (int h = 0; h < 6; h++)
            if (hidx == h) { inv_sel = 1.f / S[h]; ad_sel = adh[h]; }

        bool act_agg = (DOUT == 32) ? actl : (actl && eo == 0);
        int dlane = (DOUT == 32) ? lane : ll;
        for (int j = start; j < end; j++) {
            int s0 = g_csr[j];
            float a = 0.f;
            uint4 v = {0,0,0,0};
            if (act_agg) {
                float e = lrelu(aef[s0 * 16 + hidx] + ad_sel);
                a = __expf(e) * inv_sel;
                v = gh[(size_t)s0 * NU4 + dlane];
            }
            float2 t;
            t = __half22float2(u2h(v.x)); f[0] += t.x * a; f[1] += t.y * a;
            t = __half22float2(u2h(v.y)); f[2] += t.x * a; f[3] += t.y * a;
            t = __half22float2(u2h(v.z)); f[4] += t.x * a; f[5] += t.y * a;
            t = __half22float2(u2h(v.w)); f[6] += t.x * a; f[7] += t.y * a;
        }
    }

    // ---- common epilogue: smem transpose, head mean + bias + SELU ----
    __syncwarp();
    if constexpr (DOUT == 32) {
        if (actl) {
            int b = lane * 8;
            #pragma unroll
            for (int k = 0; k < 8; k++) sw[b + k] = f[k];
        }
        __syncwarp();
        float o0 = sw[lane] + sw[32 + lane] + sw[64 + lane] +
                   sw[96 + lane] + sw[128 + lane] + sw[160 + lane];
        out[n * 32 + lane] = selu_f(o0 * (1.f / 6.f) + bias[lane]);
    } else {
        if (actl) {
            int b = eo * 96 + ll * 8;
            #pragma unroll
            for (int k = 0; k < 8; k++) sw[b + k] = f[k];
        }
        __syncwarp();
        if (lane < 16) {
            float o0 = 0.f;
            #pragma unroll
            for (int h = 0; h < 6; h++)
                o0 += sw[h * 16 + lane] + sw[96 + h * 16 + lane];
            out[n * 16 + lane] = selu_f(o0 * (1.f / 6.f) + bias[lane]);
        }
    }
}

// ---------------- host launcher ---------------------------------------------
extern "C" void kernel_launch(void* const* d_in, const int* in_sizes, int n_in,
                              void* d_out, int out_size) {
    (void)in_sizes; (void)n_in; (void)out_size;
    const float* x     = (const float*)d_in[0];
    const int*   ei    = (const int*)d_in[1];
    const float* lin_w = (const float*)d_in[2];
    const float* lin_b = (const float*)d_in[3];
    const float* W[4]  = { (const float*)d_in[4],  (const float*)d_in[8],
                           (const float*)d_in[12], (const float*)d_in[16] };
    const float* AS[4] = { (const float*)d_in[5],  (const float*)d_in[9],
                           (const float*)d_in[13], (const float*)d_in[17] };
    const float* AD[4] = { (const float*)d_in[6],  (const float*)d_in[10],
                           (const float*)d_in[14], (const float*)d_in[18] };
    const float* B[4]  = { (const float*)d_in[7],  (const float*)d_in[11],
                           (const float*)d_in[15], (const float*)d_in[19] };
    float* out = (float*)d_out;

    float* g_hin_ptr = nullptr;
    cudaGetSymbolAddress((void**)&g_hin_ptr, g_hin4);

    const int gat_blocks = NN / 8;

    // 0: count + lin0 + wa
    k_count_lin0<<<CNT_BLOCKS + LIN0_BLOCKS + 1, 256>>>(
        ei, x, lin_w, lin_b,
        W[0], AS[0], AD[0], W[1], AS[1], AD[1],
        W[2], AS[2], AD[2], W[3], AS[3], AD[3]);
    // 1: scan
    k_scan<<<1, 1024>>>();
    // 2: scatter + feat layer 1 (fused, independent block ranges)
    k_scatter_feat1<<<SCAT_BLOCKS + NBT1 + NBA2, 256>>>(ei, W[0]);
    // 3: gat layer 1   <- ncu capture target
    k_gat<32><<<gat_blocks, 256>>>(B[0], g_hin_ptr);
    // 4-5: layer 2
    {
        constexpr int nbt = CDIV(CDIV((NN / 4) * 48, 256), TILES);
        k_feat<32, 32, 192, 1, false><<<nbt + NBA2, 256>>>(W[1]);
    }
    k_gat<32><<<gat_blocks, 256>>>(B[1], g_hin_ptr);
    // 6-7: layer 3
    {
        constexpr int nbt = CDIV(CDIV((NN / 4) * 24, 256), TILES);
        k_feat<32, 16, 96, 2, false><<<nbt + NBA2, 256>>>(W[2]);
    }
    k_gat<16><<<gat_blocks, 256>>>(B[2], g_hin_ptr);
    // 8-9: layer 4 (+cursor re-zero for next call)
    {
        constexpr int nbt = CDIV(CDIV((NN / 4) * 4, 256), TILES);
        k_feat<16, 2, 16, 3, true><<<nbt + NBA2 + CDIV(NN, 256), 256>>>(W[3]);
    }
    k_gat<2><<<gat_blocks, 256>>>(B[3], out);
}